// round 4
// baseline (speedup 1.0000x reference)
#include <cuda_runtime.h>
#include <cuda_bf16.h>
#include <math.h>
#include <stdint.h>

#define Bx 4
#define T 1024
#define D 512
#define H 8
#define DH 64
#define W1 32
#define WB 65
#define FF 2048
#define CE 1024
#define KS 31
#define NTOK (Bx*T)
#define EPS 1e-5f

// ---------------- scratch (static device globals; no allocation) ----------------
__device__ __align__(16) float g_xln[NTOK*D];
__device__ __align__(16) float g_ff [NTOK*FF];
__device__ __align__(16) float g_h  [NTOK*D];
__device__ __align__(16) float g_q  [NTOK*D];
__device__ __align__(16) float g_k  [NTOK*D];
__device__ __align__(16) float g_v  [NTOK*D];
__device__ __align__(16) float g_cf [NTOK*CE];
__device__ __align__(16) float g_u  [NTOK*D];
__device__ __align__(16) float g_v2 [NTOK*D];

// ---------------- small PTX helpers ----------------
// NOTE: mma.sync tf32 reads a 32-bit register and uses the top 19 bits; we feed
// raw fp32 bits (truncation) and skip cvt.rna.tf32 entirely — saves ~1/3 of the
// mainloop instruction stream at a cost of ~1 mantissa bit of rounding.
__device__ __forceinline__ void mma_tf32(float* c, const uint32_t* a, const uint32_t* b){
    asm volatile(
        "mma.sync.aligned.m16n8k8.row.col.f32.tf32.tf32.f32 "
        "{%0,%1,%2,%3}, {%4,%5,%6,%7}, {%8,%9}, {%0,%1,%2,%3};"
        : "+f"(c[0]), "+f"(c[1]), "+f"(c[2]), "+f"(c[3])
        : "r"(a[0]), "r"(a[1]), "r"(a[2]), "r"(a[3]), "r"(b[0]), "r"(b[1]));
}
__device__ __forceinline__ void cpasync16(void* smem, const void* g){
    uint32_t s = (uint32_t)__cvta_generic_to_shared(smem);
    asm volatile("cp.async.cg.shared.global [%0], [%1], 16;" :: "r"(s), "l"(g));
}
__device__ __forceinline__ void cp_commit(){ asm volatile("cp.async.commit_group;"); }
template<int N> __device__ __forceinline__ void cp_wait(){ asm volatile("cp.async.wait_group %0;" :: "n"(N)); }

// ---------------- LayerNorm: one block (128 thr) per row of 512 ----------------
__device__ __forceinline__ float warpSum(float v){
    #pragma unroll
    for (int o=16;o;o>>=1) v += __shfl_xor_sync(0xffffffffu, v, o);
    return v;
}

__global__ void ln_kernel(const float* __restrict__ X, const float* __restrict__ gam,
                          const float* __restrict__ bet, float* __restrict__ Y){
    int row = blockIdx.x;
    int tid = threadIdx.x;                      // 128 threads, 4 floats each
    const float4* x4 = (const float4*)(X + (size_t)row*D);
    float4 v = x4[tid];
    float s  = v.x+v.y+v.z+v.w;
    float ss = v.x*v.x+v.y*v.y+v.z*v.z+v.w*v.w;
    __shared__ float red[8];
    s = warpSum(s); ss = warpSum(ss);
    int wid = tid>>5, lane = tid&31;
    if (lane==0){ red[wid]=s; red[4+wid]=ss; }
    __syncthreads();
    if (tid==0){
        float ts  = red[0]+red[1]+red[2]+red[3];
        float tss = red[4]+red[5]+red[6]+red[7];
        float mean = ts*(1.0f/D);
        float var  = tss*(1.0f/D) - mean*mean;
        red[0]=mean; red[1]=rsqrtf(var + EPS);
    }
    __syncthreads();
    float mean = red[0], rstd = red[1];
    float4 g = ((const float4*)gam)[tid];
    float4 b = ((const float4*)bet)[tid];
    float4 o;
    o.x=(v.x-mean)*rstd*g.x+b.x; o.y=(v.y-mean)*rstd*g.y+b.y;
    o.z=(v.z-mean)*rstd*g.z+b.z; o.w=(v.w-mean)*rstd*g.w+b.w;
    ((float4*)(Y + (size_t)row*D))[tid]=o;
}

// ---------------- TF32 tensor-core GEMM 128x128, BK=16, warp 64x32 ----------------
#define ASTRIDE 20   // BK(16)+4 pad  -> conflict-free A frag loads
#define BSTRIDE 136  // BN(128)+8 pad -> conflict-free B frag loads

// Shared mainloop: accumulates C_tile = A_tile * W_tile over K.
// Caller provides global pointers already offset to the CTA tile origin.
__device__ __forceinline__ void gemm_core(
    const float* __restrict__ Ag, const float* __restrict__ Bg,
    int K, int N, float acc[4][4][4],
    float* As0, float* As1, float* Bs0, float* Bs1,
    int aRow, int aCol4, int bRow, int bCol4,
    int wm, int wn, int r, int cc)
{
    float* AsBuf[2] = {As0, As1};
    float* BsBuf[2] = {Bs0, Bs1};

    const int nk = K >> 4;
    {
        float* as = AsBuf[0]; float* bs = BsBuf[0];
        cpasync16(as + aRow*ASTRIDE + aCol4,        Ag);
        cpasync16(as + (aRow+64)*ASTRIDE + aCol4,   Ag + (size_t)64*K);
        cpasync16(bs + bRow*BSTRIDE + bCol4,        Bg);
        cpasync16(bs + (bRow+8)*BSTRIDE + bCol4,    Bg + (size_t)8*N);
    }
    cp_commit();

    for (int it=0; it<nk; it++){
        int cur = it & 1;
        if (it+1 < nk){
            int nxt = cur ^ 1;
            const float* Agn = Ag + (size_t)(it+1)*16;
            const float* Bgn = Bg + (size_t)(it+1)*16*N;
            float* as = AsBuf[nxt]; float* bs = BsBuf[nxt];
            cpasync16(as + aRow*ASTRIDE + aCol4,        Agn);
            cpasync16(as + (aRow+64)*ASTRIDE + aCol4,   Agn + (size_t)64*K);
            cpasync16(bs + bRow*BSTRIDE + bCol4,        Bgn);
            cpasync16(bs + (bRow+8)*BSTRIDE + bCol4,    Bgn + (size_t)8*N);
        }
        cp_commit();
        cp_wait<1>();
        __syncthreads();

        const float* as = AsBuf[cur];
        const float* bs = BsBuf[cur];
        const uint32_t* asu = (const uint32_t*)as;
        const uint32_t* bsu = (const uint32_t*)bs;
        #pragma unroll
        for (int ks=0; ks<2; ks++){
            uint32_t af[4][4];
            uint32_t bf[4][2];
            #pragma unroll
            for (int mi=0; mi<4; mi++){
                int base = (wm*64 + mi*16 + r)*ASTRIDE + ks*8 + cc;
                af[mi][0] = asu[base];
                af[mi][1] = asu[base + 8*ASTRIDE];
                af[mi][2] = asu[base + 4];
                af[mi][3] = asu[base + 8*ASTRIDE + 4];
            }
            #pragma unroll
            for (int ni=0; ni<4; ni++){
                int base = (ks*8 + cc)*BSTRIDE + wn*32 + ni*8 + r;
                bf[ni][0] = bsu[base];
                bf[ni][1] = bsu[base + 4*BSTRIDE];
            }
            #pragma unroll
            for (int mi=0; mi<4; mi++)
                #pragma unroll
                for (int ni=0; ni<4; ni++)
                    mma_tf32(acc[mi][ni], af[mi], bf[ni]);
        }
        __syncthreads();
    }
}

// MODE: 0 = C=AW+bias ; 1 = swish(AW+bias) ; 2 = C=R+alpha*(AW+bias)
template<int MODE>
__global__ __launch_bounds__(256, 2) void tgemm_kernel(
    const float* __restrict__ A, const float* __restrict__ W,
    const float* __restrict__ bias, const float* __restrict__ R,
    float* __restrict__ C, int M, int N, int K, float alpha)
{
    __shared__ float As[2][128*ASTRIDE];
    __shared__ float Bs[2][16*BSTRIDE];

    const int tid  = threadIdx.x;
    const int lane = tid & 31;
    const int wid  = tid >> 5;
    const int wm   = wid >> 2;
    const int wn   = wid & 3;
    const int bx = blockIdx.x, by = blockIdx.y;

    const int aRow  = tid >> 2;
    const int aCol4 = (tid & 3) * 4;
    const int bRow  = tid >> 5;
    const int bCol4 = (tid & 31) * 4;
    const int r  = lane >> 2;
    const int cc = lane & 3;

    const float* Ag = A + (size_t)(by*128 + aRow)*K + aCol4;
    const float* Bg = W + (size_t)bRow*N + bx*128 + bCol4;

    float acc[4][4][4];
    #pragma unroll
    for (int i=0;i<4;i++)
        #pragma unroll
        for (int j=0;j<4;j++)
            #pragma unroll
            for (int q=0;q<4;q++) acc[i][j][q]=0.0f;

    gemm_core(Ag, Bg, K, N, acc, As[0], As[1], Bs[0], Bs[1],
              aRow, aCol4, bRow, bCol4, wm, wn, r, cc);

    #pragma unroll
    for (int mi=0; mi<4; mi++){
        int gr0 = by*128 + wm*64 + mi*16 + r;
        #pragma unroll
        for (int ni=0; ni<4; ni++){
            int col = bx*128 + wn*32 + ni*8 + cc*2;
            float b0 = bias[col], b1 = bias[col+1];
            #pragma unroll
            for (int half=0; half<2; half++){
                int row = gr0 + half*8;
                float v0 = acc[mi][ni][half*2+0] + b0;
                float v1 = acc[mi][ni][half*2+1] + b1;
                if (MODE==1){ v0 = v0/(1.0f+expf(-v0)); v1 = v1/(1.0f+expf(-v1)); }
                if (MODE==2){
                    const float2 rr = *(const float2*)(R + (size_t)row*N + col);
                    v0 = rr.x + alpha*v0; v1 = rr.y + alpha*v1;
                }
                *(float2*)(C + (size_t)row*N + col) = make_float2(v0, v1);
            }
        }
    }
}

// Fused QKV: one launch, grid.x = 3*(D/128); sel picks {Wq,Wk,Wv}.
__global__ __launch_bounds__(256, 2) void qkv_kernel(
    const float* __restrict__ A,
    const float* __restrict__ Wq, const float* __restrict__ Wk, const float* __restrict__ Wv,
    const float* __restrict__ bq, const float* __restrict__ bk, const float* __restrict__ bv,
    float* __restrict__ Q, float* __restrict__ Ko, float* __restrict__ V)
{
    __shared__ float As[2][128*ASTRIDE];
    __shared__ float Bs[2][16*BSTRIDE];

    const int tid  = threadIdx.x;
    const int lane = tid & 31;
    const int wid  = tid >> 5;
    const int wm   = wid >> 2;
    const int wn   = wid & 3;
    const int by = blockIdx.y;
    const int sel = blockIdx.x >> 2;        // 0=q 1=k 2=v
    const int bx  = blockIdx.x & 3;

    const float* W  = sel==0 ? Wq : (sel==1 ? Wk : Wv);
    const float* bb = sel==0 ? bq : (sel==1 ? bk : bv);
    float* C        = sel==0 ? Q  : (sel==1 ? Ko : V);
    const float alpha = sel==0 ? 0.125f : 1.0f;

    const int aRow  = tid >> 2;
    const int aCol4 = (tid & 3) * 4;
    const int bRow  = tid >> 5;
    const int bCol4 = (tid & 31) * 4;
    const int r  = lane >> 2;
    const int cc = lane & 3;

    const float* Ag = A + (size_t)(by*128 + aRow)*D + aCol4;
    const float* Bg = W + (size_t)bRow*D + bx*128 + bCol4;

    float acc[4][4][4];
    #pragma unroll
    for (int i=0;i<4;i++)
        #pragma unroll
        for (int j=0;j<4;j++)
            #pragma unroll
            for (int q=0;q<4;q++) acc[i][j][q]=0.0f;

    gemm_core(Ag, Bg, D, D, acc, As[0], As[1], Bs[0], Bs[1],
              aRow, aCol4, bRow, bCol4, wm, wn, r, cc);

    #pragma unroll
    for (int mi=0; mi<4; mi++){
        int gr0 = by*128 + wm*64 + mi*16 + r;
        #pragma unroll
        for (int ni=0; ni<4; ni++){
            int col = bx*128 + wn*32 + ni*8 + cc*2;
            float b0 = bb[col], b1 = bb[col+1];
            #pragma unroll
            for (int half=0; half<2; half++){
                int row = gr0 + half*8;
                float v0 = (acc[mi][ni][half*2+0] + b0) * alpha;
                float v1 = (acc[mi][ni][half*2+1] + b1) * alpha;
                *(float2*)(C + (size_t)row*D + col) = make_float2(v0, v1);
            }
        }
    }
}

// ---------------- banded attention: warp per (b,t,h); h += ctx in place ----------------
__global__ void attn_kernel(const float* __restrict__ Q, const float* __restrict__ Kt,
                            const float* __restrict__ V, float* __restrict__ Hh,
                            float* __restrict__ P){
    __shared__ float sc[8][WB+7];
    int warp = threadIdx.x >> 5;
    int lane = threadIdx.x & 31;
    int wg = blockIdx.x*8 + warp;          // 0 .. B*T*H-1
    int h = wg & (H-1);
    int t = (wg >> 3) & (T-1);
    int b = wg >> 13;
    size_t base = ((size_t)(b*T + t))*D + h*DH;
    int d0 = lane*2;
    float q0 = Q[base + d0], q1 = Q[base + d0 + 1];
    float* s = sc[warp];
    for (int w=0; w<WB; w++){
        int src = t - W1 + w;
        float sv = -1e9f;
        if ((unsigned)src < (unsigned)T){
            size_t kb = ((size_t)(b*T + src))*D + h*DH;
            float p = q0*Kt[kb+d0] + q1*Kt[kb+d0+1];
            #pragma unroll
            for (int o=16;o;o>>=1) p += __shfl_xor_sync(0xffffffffu, p, o);
            sv = p;
        }
        if (lane==0) s[w] = sv;
    }
    __syncwarp();
    float m = -1e30f;
    for (int w=lane; w<WB; w+=32) m = fmaxf(m, s[w]);
    #pragma unroll
    for (int o=16;o;o>>=1) m = fmaxf(m, __shfl_xor_sync(0xffffffffu, m, o));
    float sum = 0.0f;
    for (int w=lane; w<WB; w+=32){ float e = expf(s[w]-m); s[w]=e; sum+=e; }
    #pragma unroll
    for (int o=16;o;o>>=1) sum += __shfl_xor_sync(0xffffffffu, sum, o);
    float inv = 1.0f/sum;
    __syncwarp();
    float* pp = P + ((size_t)((b*T + t)*H + h))*WB;
    for (int w=lane; w<WB; w+=32) pp[w] = s[w]*inv;
    float a0=0.0f, a1=0.0f;
    for (int w=0; w<WB; w++){
        int src = t - W1 + w;
        if ((unsigned)src >= (unsigned)T) continue;
        float p = s[w]*inv;
        size_t vb = ((size_t)(b*T + src))*D + h*DH;
        a0 += p*V[vb+d0];
        a1 += p*V[vb+d0+1];
    }
    Hh[base+d0]   += a0;
    Hh[base+d0+1] += a1;
}

// ---------------- GLU: u = a * sigmoid(gate) ----------------
__global__ void glu_kernel(const float* __restrict__ CF, float* __restrict__ U){
    int idx = blockIdx.x*blockDim.x + threadIdx.x;     // NTOK*D
    int r = idx >> 9;
    int c = idx & (D-1);
    float a = CF[(size_t)r*CE + c];
    float g = CF[(size_t)r*CE + D + c];
    U[idx] = a / (1.0f + expf(-g));
}

// ---------------- depthwise conv (K=31) + bn + swish ----------------
__global__ void dwconv_kernel(const float* __restrict__ U, const float* __restrict__ Wd,
                              const float* __restrict__ bd, const float* __restrict__ bg,
                              const float* __restrict__ bb, float* __restrict__ O){
    int idx = blockIdx.x*blockDim.x + threadIdx.x;     // NTOK*D
    int c = idx & (D-1);
    int tt = idx >> 9;
    int t = tt & (T-1);
    int b = tt >> 10;
    float acc = bd[c];
    #pragma unroll
    for (int k=0;k<KS;k++){
        int src = t - (KS-1)/2 + k;
        if ((unsigned)src < (unsigned)T)
            acc = fmaf(U[((size_t)(b*T+src))*D + c], Wd[k*D + c], acc);
    }
    const float bns = 0.99999500003749937f;            // rsqrt(1+1e-5)
    acc = acc*bns*bg[c] + bb[c];
    O[idx] = acc / (1.0f + expf(-acc));                // swish
}

// ---------------- host ----------------
static float* symaddr(const void* s){
    void* p = nullptr;
    cudaGetSymbolAddress(&p, s);
    return (float*)p;
}

extern "C" void kernel_launch(void* const* d_in, const int* in_sizes, int n_in,
                              void* d_out, int out_size){
    const float* x         = (const float*)d_in[0];
    const float* ff1_ln_g  = (const float*)d_in[1];
    const float* ff1_ln_b  = (const float*)d_in[2];
    const float* ff1_w1    = (const float*)d_in[3];
    const float* ff1_b1    = (const float*)d_in[4];
    const float* ff1_w2    = (const float*)d_in[5];
    const float* ff1_b2    = (const float*)d_in[6];
    const float* ff2_ln_g  = (const float*)d_in[7];
    const float* ff2_ln_b  = (const float*)d_in[8];
    const float* ff2_w1    = (const float*)d_in[9];
    const float* ff2_b1    = (const float*)d_in[10];
    const float* ff2_w2    = (const float*)d_in[11];
    const float* ff2_b2    = (const float*)d_in[12];
    const float* wq        = (const float*)d_in[13];
    const float* bq        = (const float*)d_in[14];
    const float* wk        = (const float*)d_in[15];
    const float* bk        = (const float*)d_in[16];
    const float* wv        = (const float*)d_in[17];
    const float* bv        = (const float*)d_in[18];
    const float* conv_ln_g = (const float*)d_in[19];
    const float* conv_ln_b = (const float*)d_in[20];
    const float* pw1_w     = (const float*)d_in[21];
    const float* pw1_b     = (const float*)d_in[22];
    const float* dw_w      = (const float*)d_in[23];
    const float* dw_b      = (const float*)d_in[24];
    const float* bn_g      = (const float*)d_in[25];
    const float* bn_b      = (const float*)d_in[26];
    const float* pw2_w     = (const float*)d_in[27];
    const float* pw2_b     = (const float*)d_in[28];
    const float* fin_ln_g  = (const float*)d_in[29];
    const float* fin_ln_b  = (const float*)d_in[30];

    float* out   = (float*)d_out;
    float* probs = out + (size_t)NTOK*D;

    float* xln = symaddr(g_xln);
    float* ff  = symaddr(g_ff);
    float* h   = symaddr(g_h);
    float* q   = symaddr(g_q);
    float* k   = symaddr(g_k);
    float* v   = symaddr(g_v);
    float* cf  = symaddr(g_cf);
    float* u   = symaddr(g_u);
    float* v2  = symaddr(g_v2);

    const int M = NTOK;
    dim3 blk(256);

    // ---- ff1 (half-scale residual) ----
    ln_kernel<<<M,128>>>(x, ff1_ln_g, ff1_ln_b, xln);
    tgemm_kernel<1><<<dim3(FF/128, M/128), blk>>>(xln, ff1_w1, ff1_b1, nullptr, ff, M, FF, D, 1.0f);
    tgemm_kernel<2><<<dim3(D/128,  M/128), blk>>>(ff,  ff1_w2, ff1_b2, x,       h,  M, D, FF, 0.5f);

    // ---- QKV (single fused launch) ----
    qkv_kernel<<<dim3(12, M/128), blk>>>(h, wq, wk, wv, bq, bk, bv, q, k, v);

    // ---- banded attention (h += ctx in place; writes probs) ----
    attn_kernel<<<(Bx*T*H)/8, 256>>>(q, k, v, h, probs);

    // ---- conv module (residual in place) ----
    ln_kernel<<<M,128>>>(h, conv_ln_g, conv_ln_b, xln);
    tgemm_kernel<0><<<dim3(CE/128, M/128), blk>>>(xln, pw1_w, pw1_b, nullptr, cf, M, CE, D, 1.0f);
    glu_kernel<<<(NTOK*D)/256, 256>>>(cf, u);
    dwconv_kernel<<<(NTOK*D)/256, 256>>>(u, dw_w, dw_b, bn_g, bn_b, v2);
    tgemm_kernel<2><<<dim3(D/128, M/128), blk>>>(v2, pw2_w, pw2_b, h, h, M, D, D, 1.0f);

    // ---- ff2 (half-scale residual, in place) ----
    ln_kernel<<<M,128>>>(h, ff2_ln_g, ff2_ln_b, xln);
    tgemm_kernel<1><<<dim3(FF/128, M/128), blk>>>(xln, ff2_w1, ff2_b1, nullptr, ff, M, FF, D, 1.0f);
    tgemm_kernel<2><<<dim3(D/128,  M/128), blk>>>(ff,  ff2_w2, ff2_b2, h,       h,  M, D, FF, 0.5f);

    // ---- final LN straight into d_out ----
    ln_kernel<<<M,128>>>(h, fin_ln_g, fin_ln_b, out);
}

// round 5
// speedup vs baseline: 1.1111x; 1.1111x over previous
#include <cuda_runtime.h>
#include <cuda_bf16.h>
#include <math.h>
#include <stdint.h>

#define Bx 4
#define T 1024
#define D 512
#define H 8
#define DH 64
#define W1 32
#define WB 65
#define FF 2048
#define CE 1024
#define KS 31
#define NTOK (Bx*T)
#define EPS 1e-5f

// ---------------- scratch (static device globals; no allocation) ----------------
__device__ __align__(16) float g_xln[NTOK*D];
__device__ __align__(16) float g_ff [NTOK*FF];
__device__ __align__(16) float g_h  [NTOK*D];
__device__ __align__(16) float g_q  [NTOK*D];
__device__ __align__(16) float g_k  [NTOK*D];
__device__ __align__(16) float g_v  [NTOK*D];
__device__ __align__(16) float g_cf [NTOK*CE];
__device__ __align__(16) float g_u  [NTOK*D];
__device__ __align__(16) float g_v2 [NTOK*D];

// ---------------- small PTX helpers ----------------
__device__ __forceinline__ void mma_tf32(float* c, const uint32_t* a, const uint32_t* b){
    asm volatile(
        "mma.sync.aligned.m16n8k8.row.col.f32.tf32.tf32.f32 "
        "{%0,%1,%2,%3}, {%4,%5,%6,%7}, {%8,%9}, {%0,%1,%2,%3};"
        : "+f"(c[0]), "+f"(c[1]), "+f"(c[2]), "+f"(c[3])
        : "r"(a[0]), "r"(a[1]), "r"(a[2]), "r"(a[3]), "r"(b[0]), "r"(b[1]));
}
__device__ __forceinline__ void ldsm_x4(uint32_t &a, uint32_t &b, uint32_t &c, uint32_t &d, uint32_t addr){
    asm volatile("ldmatrix.sync.aligned.m8n8.x4.shared.b16 {%0,%1,%2,%3}, [%4];"
        : "=r"(a), "=r"(b), "=r"(c), "=r"(d) : "r"(addr));
}
__device__ __forceinline__ void cpasync16(void* smem, const void* g){
    uint32_t s = (uint32_t)__cvta_generic_to_shared(smem);
    asm volatile("cp.async.cg.shared.global [%0], [%1], 16;" :: "r"(s), "l"(g));
}
__device__ __forceinline__ void cp_commit(){ asm volatile("cp.async.commit_group;"); }
template<int N> __device__ __forceinline__ void cp_wait(){ asm volatile("cp.async.wait_group %0;" :: "n"(N)); }

// ---------------- LayerNorm: one block (128 thr) per row of 512 ----------------
__device__ __forceinline__ float warpSum(float v){
    #pragma unroll
    for (int o=16;o;o>>=1) v += __shfl_xor_sync(0xffffffffu, v, o);
    return v;
}

__global__ void ln_kernel(const float* __restrict__ X, const float* __restrict__ gam,
                          const float* __restrict__ bet, float* __restrict__ Y){
    int row = blockIdx.x;
    int tid = threadIdx.x;
    const float4* x4 = (const float4*)(X + (size_t)row*D);
    float4 v = x4[tid];
    float s  = v.x+v.y+v.z+v.w;
    float ss = v.x*v.x+v.y*v.y+v.z*v.z+v.w*v.w;
    __shared__ float red[8];
    s = warpSum(s); ss = warpSum(ss);
    int wid = tid>>5, lane = tid&31;
    if (lane==0){ red[wid]=s; red[4+wid]=ss; }
    __syncthreads();
    if (tid==0){
        float ts  = red[0]+red[1]+red[2]+red[3];
        float tss = red[4]+red[5]+red[6]+red[7];
        float mean = ts*(1.0f/D);
        float var  = tss*(1.0f/D) - mean*mean;
        red[0]=mean; red[1]=rsqrtf(var + EPS);
    }
    __syncthreads();
    float mean = red[0], rstd = red[1];
    float4 g = ((const float4*)gam)[tid];
    float4 b = ((const float4*)bet)[tid];
    float4 o;
    o.x=(v.x-mean)*rstd*g.x+b.x; o.y=(v.y-mean)*rstd*g.y+b.y;
    o.z=(v.z-mean)*rstd*g.z+b.z; o.w=(v.w-mean)*rstd*g.w+b.w;
    ((float4*)(Y + (size_t)row*D))[tid]=o;
}

// ---------------- TF32 tensor-core GEMM 128x128, BK=16, 3-stage cp.async ----------------
#define ASTRIDE 20    // BK(16)+4 pad
#define BSTRIDE 136   // BN(128)+8 pad
#define A_WORDS (128*ASTRIDE)
#define B_WORDS (16*BSTRIDE)
#define STAGE_WORDS (A_WORDS + B_WORDS)
#define STAGES 3
#define GSMEM_BYTES (STAGES*STAGE_WORDS*4)

// Shared mainloop. One __syncthreads per k-tile; tile `it` is guaranteed landed by
// wait_group<1> because it is always >=2 commit-groups older than the newest group.
__device__ __forceinline__ void gemm_core(
    const float* __restrict__ Ag, const float* __restrict__ Bg,
    int K, int N, float acc[4][4][4], float* smem,
    int aRow, int aCol4, int bRow, int bCol4,
    int wm, int wn, int r, int cc)
{
    const int nk = K >> 4;
    const int lane = threadIdx.x & 31;
    const int mat  = lane >> 3;         // 0..3 (ldmatrix source matrix id)
    const int lrow = lane & 7;

    auto issue = [&](int tile, int stage){
        float* as = smem + stage*STAGE_WORDS;
        float* bs = as + A_WORDS;
        const float* Agn = Ag + (size_t)tile*16;
        const float* Bgn = Bg + (size_t)tile*16*N;
        cpasync16(as + aRow*ASTRIDE + aCol4,        Agn);
        cpasync16(as + (aRow+64)*ASTRIDE + aCol4,   Agn + (size_t)64*K);
        cpasync16(bs + bRow*BSTRIDE + bCol4,        Bgn);
        cpasync16(bs + (bRow+8)*BSTRIDE + bCol4,    Bgn + (size_t)8*N);
    };

    issue(0, 0); cp_commit();
    issue(1, 1); cp_commit();

    // per-lane ldmatrix row address components (A):
    // row = wm*64 + mi*16 + (mat&1)*8 + lrow ; col32 = ks*8 + (mat>>1)*4
    const int arow_l = wm*64 + (mat&1)*8 + lrow;
    const int acol_l = (mat>>1)*4;

    for (int it=0; it<nk; it++){
        int cur = it % STAGES;
        cp_wait<1>();
        __syncthreads();
        if (it+2 < nk) issue(it+2, (it+2)%STAGES);
        cp_commit();

        float* as = smem + cur*STAGE_WORDS;
        float* bs = as + A_WORDS;
        uint32_t as_base = (uint32_t)__cvta_generic_to_shared(as);
        const uint32_t* bsu = (const uint32_t*)bs;

        #pragma unroll
        for (int ks=0; ks<2; ks++){
            uint32_t af[4][4];
            #pragma unroll
            for (int mi=0; mi<4; mi++){
                uint32_t addr = as_base + (uint32_t)(((arow_l + mi*16)*ASTRIDE) + ks*8 + acol_l)*4u;
                ldsm_x4(af[mi][0], af[mi][1], af[mi][2], af[mi][3], addr);
            }
            uint32_t bf[4][2];
            #pragma unroll
            for (int ni=0; ni<4; ni++){
                int base = (ks*8 + cc)*BSTRIDE + wn*32 + ni*8 + r;
                bf[ni][0] = bsu[base];
                bf[ni][1] = bsu[base + 4*BSTRIDE];
            }
            #pragma unroll
            for (int mi=0; mi<4; mi++)
                #pragma unroll
                for (int ni=0; ni<4; ni++)
                    mma_tf32(acc[mi][ni], af[mi], bf[ni]);
        }
    }
}

// MODE: 0 = C=AW+bias ; 1 = swish(AW+bias) ; 2 = C=R+alpha*(AW+bias)
template<int MODE>
__global__ __launch_bounds__(256, 2) void tgemm_kernel(
    const float* __restrict__ A, const float* __restrict__ W,
    const float* __restrict__ bias, const float* __restrict__ R,
    float* __restrict__ C, int M, int N, int K, float alpha)
{
    extern __shared__ float smem[];

    const int tid  = threadIdx.x;
    const int lane = tid & 31;
    const int wid  = tid >> 5;
    const int wm   = wid >> 2;
    const int wn   = wid & 3;
    const int bx = blockIdx.x, by = blockIdx.y;

    const int aRow  = tid >> 2;
    const int aCol4 = (tid & 3) * 4;
    const int bRow  = tid >> 5;
    const int bCol4 = (tid & 31) * 4;
    const int r  = lane >> 2;
    const int cc = lane & 3;

    const float* Ag = A + (size_t)(by*128 + aRow)*K + aCol4;
    const float* Bg = W + (size_t)bRow*N + bx*128 + bCol4;

    float acc[4][4][4];
    #pragma unroll
    for (int i=0;i<4;i++)
        #pragma unroll
        for (int j=0;j<4;j++)
            #pragma unroll
            for (int q=0;q<4;q++) acc[i][j][q]=0.0f;

    gemm_core(Ag, Bg, K, N, acc, smem, aRow, aCol4, bRow, bCol4, wm, wn, r, cc);

    #pragma unroll
    for (int mi=0; mi<4; mi++){
        int gr0 = by*128 + wm*64 + mi*16 + r;
        #pragma unroll
        for (int ni=0; ni<4; ni++){
            int col = bx*128 + wn*32 + ni*8 + cc*2;
            float b0 = bias[col], b1 = bias[col+1];
            #pragma unroll
            for (int half=0; half<2; half++){
                int row = gr0 + half*8;
                float v0 = acc[mi][ni][half*2+0] + b0;
                float v1 = acc[mi][ni][half*2+1] + b1;
                if (MODE==1){ v0 = v0/(1.0f+expf(-v0)); v1 = v1/(1.0f+expf(-v1)); }
                if (MODE==2){
                    const float2 rr = *(const float2*)(R + (size_t)row*N + col);
                    v0 = rr.x + alpha*v0; v1 = rr.y + alpha*v1;
                }
                *(float2*)(C + (size_t)row*N + col) = make_float2(v0, v1);
            }
        }
    }
}

// Fused QKV: one launch, grid.x = 3*(D/128); sel picks {Wq,Wk,Wv}.
__global__ __launch_bounds__(256, 2) void qkv_kernel(
    const float* __restrict__ A,
    const float* __restrict__ Wq, const float* __restrict__ Wk, const float* __restrict__ Wv,
    const float* __restrict__ bq, const float* __restrict__ bk, const float* __restrict__ bv,
    float* __restrict__ Q, float* __restrict__ Ko, float* __restrict__ V)
{
    extern __shared__ float smem[];

    const int tid  = threadIdx.x;
    const int lane = tid & 31;
    const int wid  = tid >> 5;
    const int wm   = wid >> 2;
    const int wn   = wid & 3;
    const int by = blockIdx.y;
    const int sel = blockIdx.x >> 2;        // 0=q 1=k 2=v
    const int bx  = blockIdx.x & 3;

    const float* W  = sel==0 ? Wq : (sel==1 ? Wk : Wv);
    const float* bb = sel==0 ? bq : (sel==1 ? bk : bv);
    float* C        = sel==0 ? Q  : (sel==1 ? Ko : V);
    const float alpha = sel==0 ? 0.125f : 1.0f;

    const int aRow  = tid >> 2;
    const int aCol4 = (tid & 3) * 4;
    const int bRow  = tid >> 5;
    const int bCol4 = (tid & 31) * 4;
    const int r  = lane >> 2;
    const int cc = lane & 3;

    const float* Ag = A + (size_t)(by*128 + aRow)*D + aCol4;
    const float* Bg = W + (size_t)bRow*D + bx*128 + bCol4;

    float acc[4][4][4];
    #pragma unroll
    for (int i=0;i<4;i++)
        #pragma unroll
        for (int j=0;j<4;j++)
            #pragma unroll
            for (int q=0;q<4;q++) acc[i][j][q]=0.0f;

    gemm_core(Ag, Bg, D, D, acc, smem, aRow, aCol4, bRow, bCol4, wm, wn, r, cc);

    #pragma unroll
    for (int mi=0; mi<4; mi++){
        int gr0 = by*128 + wm*64 + mi*16 + r;
        #pragma unroll
        for (int ni=0; ni<4; ni++){
            int col = bx*128 + wn*32 + ni*8 + cc*2;
            float b0 = bb[col], b1 = bb[col+1];
            #pragma unroll
            for (int half=0; half<2; half++){
                int row = gr0 + half*8;
                float v0 = (acc[mi][ni][half*2+0] + b0) * alpha;
                float v1 = (acc[mi][ni][half*2+1] + b1) * alpha;
                *(float2*)(C + (size_t)row*D + col) = make_float2(v0, v1);
            }
        }
    }
}

// ---------------- banded attention: warp per (b,t,h); h += ctx in place ----------------
__global__ void attn_kernel(const float* __restrict__ Q, const float* __restrict__ Kt,
                            const float* __restrict__ V, float* __restrict__ Hh,
                            float* __restrict__ P){
    __shared__ float sc[8][WB+7];
    int warp = threadIdx.x >> 5;
    int lane = threadIdx.x & 31;
    int wg = blockIdx.x*8 + warp;
    int h = wg & (H-1);
    int t = (wg >> 3) & (T-1);
    int b = wg >> 13;
    size_t base = ((size_t)(b*T + t))*D + h*DH;
    int d0 = lane*2;
    float q0 = Q[base + d0], q1 = Q[base + d0 + 1];
    float* s = sc[warp];
    for (int w=0; w<WB; w++){
        int src = t - W1 + w;
        float sv = -1e9f;
        if ((unsigned)src < (unsigned)T){
            size_t kb = ((size_t)(b*T + src))*D + h*DH;
            float p = q0*Kt[kb+d0] + q1*Kt[kb+d0+1];
            #pragma unroll
            for (int o=16;o;o>>=1) p += __shfl_xor_sync(0xffffffffu, p, o);
            sv = p;
        }
        if (lane==0) s[w] = sv;
    }
    __syncwarp();
    float m = -1e30f;
    for (int w=lane; w<WB; w+=32) m = fmaxf(m, s[w]);
    #pragma unroll
    for (int o=16;o;o>>=1) m = fmaxf(m, __shfl_xor_sync(0xffffffffu, m, o));
    float sum = 0.0f;
    for (int w=lane; w<WB; w+=32){ float e = expf(s[w]-m); s[w]=e; sum+=e; }
    #pragma unroll
    for (int o=16;o;o>>=1) sum += __shfl_xor_sync(0xffffffffu, sum, o);
    float inv = 1.0f/sum;
    __syncwarp();
    float* pp = P + ((size_t)((b*T + t)*H + h))*WB;
    for (int w=lane; w<WB; w+=32) pp[w] = s[w]*inv;
    float a0=0.0f, a1=0.0f;
    for (int w=0; w<WB; w++){
        int src = t - W1 + w;
        if ((unsigned)src >= (unsigned)T) continue;
        float p = s[w]*inv;
        size_t vb = ((size_t)(b*T + src))*D + h*DH;
        a0 += p*V[vb+d0];
        a1 += p*V[vb+d0+1];
    }
    Hh[base+d0]   += a0;
    Hh[base+d0+1] += a1;
}

// ---------------- GLU: u = a * sigmoid(gate) ----------------
__global__ void glu_kernel(const float* __restrict__ CF, float* __restrict__ U){
    int idx = blockIdx.x*blockDim.x + threadIdx.x;
    int r = idx >> 9;
    int c = idx & (D-1);
    float a = CF[(size_t)r*CE + c];
    float g = CF[(size_t)r*CE + D + c];
    U[idx] = a / (1.0f + expf(-g));
}

// ---------------- depthwise conv (K=31) + bn + swish ----------------
__global__ void dwconv_kernel(const float* __restrict__ U, const float* __restrict__ Wd,
                              const float* __restrict__ bd, const float* __restrict__ bg,
                              const float* __restrict__ bb, float* __restrict__ O){
    int idx = blockIdx.x*blockDim.x + threadIdx.x;
    int c = idx & (D-1);
    int tt = idx >> 9;
    int t = tt & (T-1);
    int b = tt >> 10;
    float acc = bd[c];
    #pragma unroll
    for (int k=0;k<KS;k++){
        int src = t - (KS-1)/2 + k;
        if ((unsigned)src < (unsigned)T)
            acc = fmaf(U[((size_t)(b*T+src))*D + c], Wd[k*D + c], acc);
    }
    const float bns = 0.99999500003749937f;            // rsqrt(1+1e-5)
    acc = acc*bns*bg[c] + bb[c];
    O[idx] = acc / (1.0f + expf(-acc));
}

// ---------------- host ----------------
static float* symaddr(const void* s){
    void* p = nullptr;
    cudaGetSymbolAddress(&p, s);
    return (float*)p;
}

extern "C" void kernel_launch(void* const* d_in, const int* in_sizes, int n_in,
                              void* d_out, int out_size){
    const float* x         = (const float*)d_in[0];
    const float* ff1_ln_g  = (const float*)d_in[1];
    const float* ff1_ln_b  = (const float*)d_in[2];
    const float* ff1_w1    = (const float*)d_in[3];
    const float* ff1_b1    = (const float*)d_in[4];
    const float* ff1_w2    = (const float*)d_in[5];
    const float* ff1_b2    = (const float*)d_in[6];
    const float* ff2_ln_g  = (const float*)d_in[7];
    const float* ff2_ln_b  = (const float*)d_in[8];
    const float* ff2_w1    = (const float*)d_in[9];
    const float* ff2_b1    = (const float*)d_in[10];
    const float* ff2_w2    = (const float*)d_in[11];
    const float* ff2_b2    = (const float*)d_in[12];
    const float* wq        = (const float*)d_in[13];
    const float* bq        = (const float*)d_in[14];
    const float* wk        = (const float*)d_in[15];
    const float* bk        = (const float*)d_in[16];
    const float* wv        = (const float*)d_in[17];
    const float* bv        = (const float*)d_in[18];
    const float* conv_ln_g = (const float*)d_in[19];
    const float* conv_ln_b = (const float*)d_in[20];
    const float* pw1_w     = (const float*)d_in[21];
    const float* pw1_b     = (const float*)d_in[22];
    const float* dw_w      = (const float*)d_in[23];
    const float* dw_b      = (const float*)d_in[24];
    const float* bn_g      = (const float*)d_in[25];
    const float* bn_b      = (const float*)d_in[26];
    const float* pw2_w     = (const float*)d_in[27];
    const float* pw2_b     = (const float*)d_in[28];
    const float* fin_ln_g  = (const float*)d_in[29];
    const float* fin_ln_b  = (const float*)d_in[30];

    float* out   = (float*)d_out;
    float* probs = out + (size_t)NTOK*D;

    float* xln = symaddr(g_xln);
    float* ff  = symaddr(g_ff);
    float* h   = symaddr(g_h);
    float* q   = symaddr(g_q);
    float* k   = symaddr(g_k);
    float* v   = symaddr(g_v);
    float* cf  = symaddr(g_cf);
    float* u   = symaddr(g_u);
    float* v2  = symaddr(g_v2);

    // opt-in to >48KB dynamic smem (idempotent; host-side config, not a graph op)
    cudaFuncSetAttribute(tgemm_kernel<0>, cudaFuncAttributeMaxDynamicSharedMemorySize, GSMEM_BYTES);
    cudaFuncSetAttribute(tgemm_kernel<1>, cudaFuncAttributeMaxDynamicSharedMemorySize, GSMEM_BYTES);
    cudaFuncSetAttribute(tgemm_kernel<2>, cudaFuncAttributeMaxDynamicSharedMemorySize, GSMEM_BYTES);
    cudaFuncSetAttribute(qkv_kernel,      cudaFuncAttributeMaxDynamicSharedMemorySize, GSMEM_BYTES);

    const int M = NTOK;
    dim3 blk(256);

    // ---- ff1 (half-scale residual) ----
    ln_kernel<<<M,128>>>(x, ff1_ln_g, ff1_ln_b, xln);
    tgemm_kernel<1><<<dim3(FF/128, M/128), blk, GSMEM_BYTES>>>(xln, ff1_w1, ff1_b1, nullptr, ff, M, FF, D, 1.0f);
    tgemm_kernel<2><<<dim3(D/128,  M/128), blk, GSMEM_BYTES>>>(ff,  ff1_w2, ff1_b2, x,       h,  M, D, FF, 0.5f);

    // ---- QKV (single fused launch) ----
    qkv_kernel<<<dim3(12, M/128), blk, GSMEM_BYTES>>>(h, wq, wk, wv, bq, bk, bv, q, k, v);

    // ---- banded attention (h += ctx in place; writes probs) ----
    attn_kernel<<<(Bx*T*H)/8, 256>>>(q, k, v, h, probs);

    // ---- conv module (residual in place) ----
    ln_kernel<<<M,128>>>(h, conv_ln_g, conv_ln_b, xln);
    tgemm_kernel<0><<<dim3(CE/128, M/128), blk, GSMEM_BYTES>>>(xln, pw1_w, pw1_b, nullptr, cf, M, CE, D, 1.0f);
    glu_kernel<<<(NTOK*D)/256, 256>>>(cf, u);
    dwconv_kernel<<<(NTOK*D)/256, 256>>>(u, dw_w, dw_b, bn_g, bn_b, v2);
    tgemm_kernel<2><<<dim3(D/128, M/128), blk, GSMEM_BYTES>>>(v2, pw2_w, pw2_b, h, h, M, D, D, 1.0f);

    // ---- ff2 (half-scale residual, in place) ----
    ln_kernel<<<M,128>>>(h, ff2_ln_g, ff2_ln_b, xln);
    tgemm_kernel<1><<<dim3(FF/128, M/128), blk, GSMEM_BYTES>>>(xln, ff2_w1, ff2_b1, nullptr, ff, M, FF, D, 1.0f);
    tgemm_kernel<2><<<dim3(D/128,  M/128), blk, GSMEM_BYTES>>>(ff,  ff2_w2, ff2_b2, h,       h,  M, D, FF, 0.5f);

    // ---- final LN straight into d_out ----
    ln_kernel<<<M,128>>>(h, fin_ln_g, fin_ln_b, out);
}

// round 6
// speedup vs baseline: 1.4383x; 1.2945x over previous
#include <cuda_runtime.h>
#include <cuda_bf16.h>
#include <math.h>
#include <stdint.h>

#define Bx 4
#define T 1024
#define D 512
#define H 8
#define DH 64
#define W1 32
#define WB 65
#define FF 2048
#define CE 1024
#define KS 31
#define NTOK (Bx*T)
#define EPS 1e-5f

typedef __nv_bfloat16 bf16;
typedef __nv_bfloat162 bf162;

// ---------------- scratch (static device globals; no allocation) ----------------
// fp32 stream
__device__ __align__(16) float g_h  [NTOK*D];
__device__ __align__(16) float g_q  [NTOK*D];
__device__ __align__(16) float g_k  [NTOK*D];
__device__ __align__(16) float g_v  [NTOK*D];
__device__ __align__(16) float g_cf [NTOK*CE];
__device__ __align__(16) float g_u  [NTOK*D];
// bf16 activations (GEMM A inputs)
__device__ __align__(16) bf16 g_xb [NTOK*D];
__device__ __align__(16) bf16 g_ffb[NTOK*FF];
__device__ __align__(16) bf16 g_hb [NTOK*D];
__device__ __align__(16) bf16 g_v2b[NTOK*D];
// bf16 weights
__device__ __align__(16) bf16 wb_f1w1[D*FF];
__device__ __align__(16) bf16 wb_f1w2[FF*D];
__device__ __align__(16) bf16 wb_f2w1[D*FF];
__device__ __align__(16) bf16 wb_f2w2[FF*D];
__device__ __align__(16) bf16 wb_q  [D*D];
__device__ __align__(16) bf16 wb_k  [D*D];
__device__ __align__(16) bf16 wb_v  [D*D];
__device__ __align__(16) bf16 wb_p1 [D*CE];
__device__ __align__(16) bf16 wb_p2 [D*D];

// ---------------- PTX helpers ----------------
__device__ __forceinline__ void mma_bf16(float* c, const uint32_t* a, const uint32_t* b){
    asm volatile(
        "mma.sync.aligned.m16n8k16.row.col.f32.bf16.bf16.f32 "
        "{%0,%1,%2,%3}, {%4,%5,%6,%7}, {%8,%9}, {%0,%1,%2,%3};"
        : "+f"(c[0]), "+f"(c[1]), "+f"(c[2]), "+f"(c[3])
        : "r"(a[0]), "r"(a[1]), "r"(a[2]), "r"(a[3]), "r"(b[0]), "r"(b[1]));
}
__device__ __forceinline__ void ldsm_x4(uint32_t &a, uint32_t &b, uint32_t &c, uint32_t &d, uint32_t addr){
    asm volatile("ldmatrix.sync.aligned.m8n8.x4.shared.b16 {%0,%1,%2,%3}, [%4];"
        : "=r"(a), "=r"(b), "=r"(c), "=r"(d) : "r"(addr));
}
__device__ __forceinline__ void ldsm_x4_t(uint32_t &a, uint32_t &b, uint32_t &c, uint32_t &d, uint32_t addr){
    asm volatile("ldmatrix.sync.aligned.m8n8.x4.trans.shared.b16 {%0,%1,%2,%3}, [%4];"
        : "=r"(a), "=r"(b), "=r"(c), "=r"(d) : "r"(addr));
}
__device__ __forceinline__ void cpasync16(void* smem, const void* g){
    uint32_t s = (uint32_t)__cvta_generic_to_shared(smem);
    asm volatile("cp.async.cg.shared.global [%0], [%1], 16;" :: "r"(s), "l"(g));
}
__device__ __forceinline__ void cp_commit(){ asm volatile("cp.async.commit_group;"); }
template<int N> __device__ __forceinline__ void cp_wait(){ asm volatile("cp.async.wait_group %0;" :: "n"(N)); }

__device__ __forceinline__ uint32_t pack_bf2(float a, float b){
    bf162 p = __floats2bfloat162_rn(a, b);
    return *(uint32_t*)&p;
}

// ---------------- weight fp32 -> bf16 (rne) ----------------
__global__ void wcvt_kernel(const float* __restrict__ s, bf16* __restrict__ d, int n){
    int i = (blockIdx.x*blockDim.x + threadIdx.x)*4;
    if (i < n){
        float4 v = *(const float4*)(s + i);
        uint2 u;
        u.x = pack_bf2(v.x, v.y);
        u.y = pack_bf2(v.z, v.w);
        *(uint2*)(d + i) = u;
    }
}

// ---------------- LayerNorm (row of 512); templated output type ----------------
__device__ __forceinline__ float warpSum(float v){
    #pragma unroll
    for (int o=16;o;o>>=1) v += __shfl_xor_sync(0xffffffffu, v, o);
    return v;
}

template<bool B16OUT>
__global__ void ln_kernel(const float* __restrict__ X, const float* __restrict__ gam,
                          const float* __restrict__ bet, void* __restrict__ Yv){
    int row = blockIdx.x;
    int tid = threadIdx.x;
    const float4* x4 = (const float4*)(X + (size_t)row*D);
    float4 v = x4[tid];
    float s  = v.x+v.y+v.z+v.w;
    float ss = v.x*v.x+v.y*v.y+v.z*v.z+v.w*v.w;
    __shared__ float red[8];
    s = warpSum(s); ss = warpSum(ss);
    int wid = tid>>5, lane = tid&31;
    if (lane==0){ red[wid]=s; red[4+wid]=ss; }
    __syncthreads();
    if (tid==0){
        float ts  = red[0]+red[1]+red[2]+red[3];
        float tss = red[4]+red[5]+red[6]+red[7];
        float mean = ts*(1.0f/D);
        float var  = tss*(1.0f/D) - mean*mean;
        red[0]=mean; red[1]=rsqrtf(var + EPS);
    }
    __syncthreads();
    float mean = red[0], rstd = red[1];
    float4 g = ((const float4*)gam)[tid];
    float4 b = ((const float4*)bet)[tid];
    float4 o;
    o.x=(v.x-mean)*rstd*g.x+b.x; o.y=(v.y-mean)*rstd*g.y+b.y;
    o.z=(v.z-mean)*rstd*g.z+b.z; o.w=(v.w-mean)*rstd*g.w+b.w;
    if (B16OUT){
        uint2 u; u.x = pack_bf2(o.x,o.y); u.y = pack_bf2(o.z,o.w);
        *(uint2*)((bf16*)Yv + (size_t)row*D + tid*4) = u;
    } else {
        ((float4*)((float*)Yv + (size_t)row*D))[tid]=o;
    }
}

// ---------------- bf16 tensor-core GEMM 128x128, BK=32, 3-stage cp.async ----------------
#define ASTR 40        // A row stride in halves (32 + 8 pad)  -> 80B, conflict-free ldsm
#define BSTR 136       // B row stride in halves (128 + 8 pad) -> 272B, conflict-free ldsm.trans
#define A_H (128*ASTR) // 5120 halves
#define B_H (32*BSTR)  // 4352 halves
#define STAGE_H (A_H + B_H)
#define STAGES 3
#define GSMEM_BYTES (STAGES*STAGE_H*2)

// Mainloop: acc += A_tile(128xK) * W_tile(Kx128), A bf16 row-major, W bf16 row-major [K][N].
__device__ __forceinline__ void gemm_core(
    const bf16* __restrict__ Ag,   // A + (rowbase)*K
    const bf16* __restrict__ Bg,   // W + colbase
    int K, int N, float acc[4][4][4], bf16* sm,
    int wm, int wn)
{
    const int tid  = threadIdx.x;
    const int lane = tid & 31;
    const int nk = K >> 5;  // BK=32

    // load assignment: A 512 chunks (16B): c -> row=c>>2, kc=c&3 ; B 512: row=c>>4, nc=c&15
    const int ac0 = tid, ac1 = tid + 256;
    const int bc0 = tid, bc1 = tid + 256;

    auto issue = [&](int tile, int stage){
        bf16* as = sm + stage*STAGE_H;
        bf16* bs = as + A_H;
        {
            int r = ac0>>2, kc = ac0&3;
            cpasync16(as + r*ASTR + kc*8, Ag + (size_t)r*K + tile*32 + kc*8);
            r = ac1>>2; kc = ac1&3;
            cpasync16(as + r*ASTR + kc*8, Ag + (size_t)r*K + tile*32 + kc*8);
        }
        {
            int r = bc0>>4, nc = bc0&15;
            cpasync16(bs + r*BSTR + nc*8, Bg + (size_t)(tile*32 + r)*N + nc*8);
            r = bc1>>4; nc = bc1&15;
            cpasync16(bs + r*BSTR + nc*8, Bg + (size_t)(tile*32 + r)*N + nc*8);
        }
    };

    issue(0, 0); cp_commit();
    issue(1, 1); cp_commit();

    // per-lane ldmatrix offsets (in halves)
    const int aoff = (wm*64 + (lane & 15))*ASTR + (lane >> 4)*8;
    const int boff = (((lane >> 4) << 3) + (lane & 7))*BSTR + wn*32 + ((lane >> 3) & 1)*8;

    for (int it=0; it<nk; it++){
        int cur = it % STAGES;
        cp_wait<1>();
        __syncthreads();
        if (it+2 < nk) issue(it+2, (it+2)%STAGES);
        cp_commit();

        bf16* as = sm + cur*STAGE_H;
        bf16* bs = as + A_H;
        uint32_t asb = (uint32_t)__cvta_generic_to_shared(as);
        uint32_t bsb = (uint32_t)__cvta_generic_to_shared(bs);

        #pragma unroll
        for (int ks=0; ks<2; ks++){
            uint32_t af[4][4];
            #pragma unroll
            for (int mi=0; mi<4; mi++){
                uint32_t addr = asb + (uint32_t)(aoff + mi*16*ASTR + ks*16)*2u;
                ldsm_x4(af[mi][0], af[mi][1], af[mi][2], af[mi][3], addr);
            }
            uint32_t bf[4][2];
            #pragma unroll
            for (int p=0; p<2; p++){
                uint32_t addr = bsb + (uint32_t)(boff + ks*16*BSTR + p*16)*2u;
                ldsm_x4_t(bf[p*2][0], bf[p*2+1][0], bf[p*2][1], bf[p*2+1][1], addr);
            }
            #pragma unroll
            for (int mi=0; mi<4; mi++)
                #pragma unroll
                for (int ni=0; ni<4; ni++)
                    mma_bf16(acc[mi][ni], af[mi], bf[ni]);
        }
    }
}

// MODE: 0 = C_f32=AW+bias ; 1 = Cb_bf16=swish(AW+bias) ; 2 = C_f32=R+alpha*(AW+bias) (+bf16 copy if WB16)
template<int MODE, bool WB16>
__global__ __launch_bounds__(256, 2) void tgemm_kernel(
    const bf16* __restrict__ A, const bf16* __restrict__ W,
    const float* __restrict__ bias, const float* __restrict__ R,
    float* __restrict__ C, bf16* __restrict__ Cb,
    int M, int N, int K, float alpha)
{
    extern __shared__ bf16 smem[];

    const int tid  = threadIdx.x;
    const int lane = tid & 31;
    const int wid  = tid >> 5;
    const int wm   = wid >> 2;
    const int wn   = wid & 3;
    const int bx = blockIdx.x, by = blockIdx.y;
    const int r  = lane >> 2;
    const int cc = lane & 3;

    const bf16* Ag = A + (size_t)(by*128)*K;
    const bf16* Bg = W + bx*128;

    float acc[4][4][4];
    #pragma unroll
    for (int i=0;i<4;i++)
        #pragma unroll
        for (int j=0;j<4;j++)
            #pragma unroll
            for (int q=0;q<4;q++) acc[i][j][q]=0.0f;

    gemm_core(Ag, Bg, K, N, acc, smem, wm, wn);

    #pragma unroll
    for (int mi=0; mi<4; mi++){
        int gr0 = by*128 + wm*64 + mi*16 + r;
        #pragma unroll
        for (int ni=0; ni<4; ni++){
            int col = bx*128 + wn*32 + ni*8 + cc*2;
            float b0 = bias[col], b1 = bias[col+1];
            #pragma unroll
            for (int half=0; half<2; half++){
                int row = gr0 + half*8;
                float v0 = acc[mi][ni][half*2+0] + b0;
                float v1 = acc[mi][ni][half*2+1] + b1;
                if (MODE==1){
                    v0 = v0/(1.0f+expf(-v0)); v1 = v1/(1.0f+expf(-v1));
                    *(uint32_t*)(Cb + (size_t)row*N + col) = pack_bf2(v0, v1);
                }
                if (MODE==0){
                    *(float2*)(C + (size_t)row*N + col) = make_float2(v0, v1);
                }
                if (MODE==2){
                    const float2 rr = *(const float2*)(R + (size_t)row*N + col);
                    v0 = rr.x + alpha*v0; v1 = rr.y + alpha*v1;
                    *(float2*)(C + (size_t)row*N + col) = make_float2(v0, v1);
                    if (WB16)
                        *(uint32_t*)(Cb + (size_t)row*N + col) = pack_bf2(v0, v1);
                }
            }
        }
    }
}

// Fused QKV (bf16 A/W, fp32 out): grid.x = 12; sel picks {Wq,Wk,Wv}.
__global__ __launch_bounds__(256, 2) void qkv_kernel(
    const bf16* __restrict__ A,
    const bf16* __restrict__ Wq, const bf16* __restrict__ Wk, const bf16* __restrict__ Wv,
    const float* __restrict__ bq, const float* __restrict__ bk, const float* __restrict__ bv,
    float* __restrict__ Q, float* __restrict__ Ko, float* __restrict__ V)
{
    extern __shared__ bf16 smem[];

    const int tid  = threadIdx.x;
    const int lane = tid & 31;
    const int wid  = tid >> 5;
    const int wm   = wid >> 2;
    const int wn   = wid & 3;
    const int by = blockIdx.y;
    const int sel = blockIdx.x >> 2;
    const int bx  = blockIdx.x & 3;
    const int r  = lane >> 2;
    const int cc = lane & 3;

    const bf16* W  = sel==0 ? Wq : (sel==1 ? Wk : Wv);
    const float* bb = sel==0 ? bq : (sel==1 ? bk : bv);
    float* C        = sel==0 ? Q  : (sel==1 ? Ko : V);
    const float alpha = sel==0 ? 0.125f : 1.0f;

    const bf16* Ag = A + (size_t)(by*128)*D;
    const bf16* Bg = W + bx*128;

    float acc[4][4][4];
    #pragma unroll
    for (int i=0;i<4;i++)
        #pragma unroll
        for (int j=0;j<4;j++)
            #pragma unroll
            for (int q=0;q<4;q++) acc[i][j][q]=0.0f;

    gemm_core(Ag, Bg, D, D, acc, smem, wm, wn);

    #pragma unroll
    for (int mi=0; mi<4; mi++){
        int gr0 = by*128 + wm*64 + mi*16 + r;
        #pragma unroll
        for (int ni=0; ni<4; ni++){
            int col = bx*128 + wn*32 + ni*8 + cc*2;
            float b0 = bb[col], b1 = bb[col+1];
            #pragma unroll
            for (int half=0; half<2; half++){
                int row = gr0 + half*8;
                float v0 = (acc[mi][ni][half*2+0] + b0) * alpha;
                float v1 = (acc[mi][ni][half*2+1] + b1) * alpha;
                *(float2*)(C + (size_t)row*D + col) = make_float2(v0, v1);
            }
        }
    }
}

// ---------------- banded attention: warp per (b,t,h); h += ctx in place ----------------
__global__ void attn_kernel(const float* __restrict__ Q, const float* __restrict__ Kt,
                            const float* __restrict__ V, float* __restrict__ Hh,
                            float* __restrict__ P){
    __shared__ float sc[8][WB+7];
    int warp = threadIdx.x >> 5;
    int lane = threadIdx.x & 31;
    int wg = blockIdx.x*8 + warp;
    int h = wg & (H-1);
    int t = (wg >> 3) & (T-1);
    int b = wg >> 13;
    size_t base = ((size_t)(b*T + t))*D + h*DH;
    int d0 = lane*2;
    float q0 = Q[base + d0], q1 = Q[base + d0 + 1];
    float* s = sc[warp];
    for (int w=0; w<WB; w++){
        int src = t - W1 + w;
        float sv = -1e9f;
        if ((unsigned)src < (unsigned)T){
            size_t kb = ((size_t)(b*T + src))*D + h*DH;
            float p = q0*Kt[kb+d0] + q1*Kt[kb+d0+1];
            #pragma unroll
            for (int o=16;o;o>>=1) p += __shfl_xor_sync(0xffffffffu, p, o);
            sv = p;
        }
        if (lane==0) s[w] = sv;
    }
    __syncwarp();
    float m = -1e30f;
    for (int w=lane; w<WB; w+=32) m = fmaxf(m, s[w]);
    #pragma unroll
    for (int o=16;o;o>>=1) m = fmaxf(m, __shfl_xor_sync(0xffffffffu, m, o));
    float sum = 0.0f;
    for (int w=lane; w<WB; w+=32){ float e = expf(s[w]-m); s[w]=e; sum+=e; }
    #pragma unroll
    for (int o=16;o;o>>=1) sum += __shfl_xor_sync(0xffffffffu, sum, o);
    float inv = 1.0f/sum;
    __syncwarp();
    float* pp = P + ((size_t)((b*T + t)*H + h))*WB;
    for (int w=lane; w<WB; w+=32) pp[w] = s[w]*inv;
    float a0=0.0f, a1=0.0f;
    for (int w=0; w<WB; w++){
        int src = t - W1 + w;
        if ((unsigned)src >= (unsigned)T) continue;
        float p = s[w]*inv;
        size_t vb = ((size_t)(b*T + src))*D + h*DH;
        a0 += p*V[vb+d0];
        a1 += p*V[vb+d0+1];
    }
    Hh[base+d0]   += a0;
    Hh[base+d0+1] += a1;
}

// ---------------- GLU ----------------
__global__ void glu_kernel(const float* __restrict__ CF, float* __restrict__ U){
    int idx = blockIdx.x*blockDim.x + threadIdx.x;
    int r = idx >> 9;
    int c = idx & (D-1);
    float a = CF[(size_t)r*CE + c];
    float g = CF[(size_t)r*CE + D + c];
    U[idx] = a / (1.0f + expf(-g));
}

// ---------------- depthwise conv (K=31) + bn + swish -> bf16 ----------------
__global__ void dwconv_kernel(const float* __restrict__ U, const float* __restrict__ Wd,
                              const float* __restrict__ bd, const float* __restrict__ bg,
                              const float* __restrict__ bb, bf16* __restrict__ O){
    int idx = blockIdx.x*blockDim.x + threadIdx.x;
    int c = idx & (D-1);
    int tt = idx >> 9;
    int t = tt & (T-1);
    int b = tt >> 10;
    float acc = bd[c];
    #pragma unroll
    for (int k=0;k<KS;k++){
        int src = t - (KS-1)/2 + k;
        if ((unsigned)src < (unsigned)T)
            acc = fmaf(U[((size_t)(b*T+src))*D + c], Wd[k*D + c], acc);
    }
    const float bns = 0.99999500003749937f;            // rsqrt(1+1e-5)
    acc = acc*bns*bg[c] + bb[c];
    acc = acc / (1.0f + expf(-acc));
    O[idx] = __float2bfloat16_rn(acc);
}

// ---------------- host ----------------
template<typename Tp>
static Tp* symaddr(const void* s){
    void* p = nullptr;
    cudaGetSymbolAddress(&p, s);
    return (Tp*)p;
}

extern "C" void kernel_launch(void* const* d_in, const int* in_sizes, int n_in,
                              void* d_out, int out_size){
    const float* x         = (const float*)d_in[0];
    const float* ff1_ln_g  = (const float*)d_in[1];
    const float* ff1_ln_b  = (const float*)d_in[2];
    const float* ff1_w1    = (const float*)d_in[3];
    const float* ff1_b1    = (const float*)d_in[4];
    const float* ff1_w2    = (const float*)d_in[5];
    const float* ff1_b2    = (const float*)d_in[6];
    const float* ff2_ln_g  = (const float*)d_in[7];
    const float* ff2_ln_b  = (const float*)d_in[8];
    const float* ff2_w1    = (const float*)d_in[9];
    const float* ff2_b1    = (const float*)d_in[10];
    const float* ff2_w2    = (const float*)d_in[11];
    const float* ff2_b2    = (const float*)d_in[12];
    const float* wq        = (const float*)d_in[13];
    const float* bq        = (const float*)d_in[14];
    const float* wk        = (const float*)d_in[15];
    const float* bk        = (const float*)d_in[16];
    const float* wv        = (const float*)d_in[17];
    const float* bv        = (const float*)d_in[18];
    const float* conv_ln_g = (const float*)d_in[19];
    const float* conv_ln_b = (const float*)d_in[20];
    const float* pw1_w     = (const float*)d_in[21];
    const float* pw1_b     = (const float*)d_in[22];
    const float* dw_w      = (const float*)d_in[23];
    const float* dw_b      = (const float*)d_in[24];
    const float* bn_g      = (const float*)d_in[25];
    const float* bn_b      = (const float*)d_in[26];
    const float* pw2_w     = (const float*)d_in[27];
    const float* pw2_b     = (const float*)d_in[28];
    const float* fin_ln_g  = (const float*)d_in[29];
    const float* fin_ln_b  = (const float*)d_in[30];

    float* out   = (float*)d_out;
    float* probs = out + (size_t)NTOK*D;

    float* h   = symaddr<float>(g_h);
    float* q   = symaddr<float>(g_q);
    float* k   = symaddr<float>(g_k);
    float* v   = symaddr<float>(g_v);
    float* cf  = symaddr<float>(g_cf);
    float* u   = symaddr<float>(g_u);
    bf16* xb   = symaddr<bf16>(g_xb);
    bf16* ffb  = symaddr<bf16>(g_ffb);
    bf16* hb   = symaddr<bf16>(g_hb);
    bf16* v2b  = symaddr<bf16>(g_v2b);
    bf16* wf1w1 = symaddr<bf16>(wb_f1w1);
    bf16* wf1w2 = symaddr<bf16>(wb_f1w2);
    bf16* wf2w1 = symaddr<bf16>(wb_f2w1);
    bf16* wf2w2 = symaddr<bf16>(wb_f2w2);
    bf16* wbq   = symaddr<bf16>(wb_q);
    bf16* wbk   = symaddr<bf16>(wb_k);
    bf16* wbv   = symaddr<bf16>(wb_v);
    bf16* wbp1  = symaddr<bf16>(wb_p1);
    bf16* wbp2  = symaddr<bf16>(wb_p2);

    cudaFuncSetAttribute(tgemm_kernel<0,false>, cudaFuncAttributeMaxDynamicSharedMemorySize, GSMEM_BYTES);
    cudaFuncSetAttribute(tgemm_kernel<1,false>, cudaFuncAttributeMaxDynamicSharedMemorySize, GSMEM_BYTES);
    cudaFuncSetAttribute(tgemm_kernel<2,true>,  cudaFuncAttributeMaxDynamicSharedMemorySize, GSMEM_BYTES);
    cudaFuncSetAttribute(tgemm_kernel<2,false>, cudaFuncAttributeMaxDynamicSharedMemorySize, GSMEM_BYTES);
    cudaFuncSetAttribute(qkv_kernel,            cudaFuncAttributeMaxDynamicSharedMemorySize, GSMEM_BYTES);

    const int M = NTOK;
    dim3 blk(256);

    // ---- weight conversions (independent; every replay) ----
    {
        const int thr = 256;
        wcvt_kernel<<<(D*FF/4+thr-1)/thr, thr>>>(ff1_w1, wf1w1, D*FF);
        wcvt_kernel<<<(FF*D/4+thr-1)/thr, thr>>>(ff1_w2, wf1w2, FF*D);
        wcvt_kernel<<<(D*FF/4+thr-1)/thr, thr>>>(ff2_w1, wf2w1, D*FF);
        wcvt_kernel<<<(FF*D/4+thr-1)/thr, thr>>>(ff2_w2, wf2w2, FF*D);
        wcvt_kernel<<<(D*D/4+thr-1)/thr, thr>>>(wq, wbq, D*D);
        wcvt_kernel<<<(D*D/4+thr-1)/thr, thr>>>(wk, wbk, D*D);
        wcvt_kernel<<<(D*D/4+thr-1)/thr, thr>>>(wv, wbv, D*D);
        wcvt_kernel<<<(D*CE/4+thr-1)/thr, thr>>>(pw1_w, wbp1, D*CE);
        wcvt_kernel<<<(D*D/4+thr-1)/thr, thr>>>(pw2_w, wbp2, D*D);
    }

    // ---- ff1 (half-scale residual) ----
    ln_kernel<true><<<M,128>>>(x, ff1_ln_g, ff1_ln_b, xb);
    tgemm_kernel<1,false><<<dim3(FF/128, M/128), blk, GSMEM_BYTES>>>(xb, wf1w1, ff1_b1, nullptr, nullptr, ffb, M, FF, D, 1.0f);
    tgemm_kernel<2,true ><<<dim3(D/128,  M/128), blk, GSMEM_BYTES>>>(ffb, wf1w2, ff1_b2, x, h, hb, M, D, FF, 0.5f);

    // ---- QKV (single fused launch, bf16 A) ----
    qkv_kernel<<<dim3(12, M/128), blk, GSMEM_BYTES>>>(hb, wbq, wbk, wbv, bq, bk, bv, q, k, v);

    // ---- banded attention (h += ctx in place; writes probs) ----
    attn_kernel<<<(Bx*T*H)/8, 256>>>(q, k, v, h, probs);

    // ---- conv module (residual in place) ----
    ln_kernel<true><<<M,128>>>(h, conv_ln_g, conv_ln_b, xb);
    tgemm_kernel<0,false><<<dim3(CE/128, M/128), blk, GSMEM_BYTES>>>(xb, wbp1, pw1_b, nullptr, cf, nullptr, M, CE, D, 1.0f);
    glu_kernel<<<(NTOK*D)/256, 256>>>(cf, u);
    dwconv_kernel<<<(NTOK*D)/256, 256>>>(u, dw_w, dw_b, bn_g, bn_b, v2b);
    tgemm_kernel<2,false><<<dim3(D/128, M/128), blk, GSMEM_BYTES>>>(v2b, wbp2, pw2_b, h, h, nullptr, M, D, D, 1.0f);

    // ---- ff2 (half-scale residual, in place) ----
    ln_kernel<true><<<M,128>>>(h, ff2_ln_g, ff2_ln_b, xb);
    tgemm_kernel<1,false><<<dim3(FF/128, M/128), blk, GSMEM_BYTES>>>(xb, wf2w1, ff2_b1, nullptr, nullptr, ffb, M, FF, D, 1.0f);
    tgemm_kernel<2,false><<<dim3(D/128,  M/128), blk, GSMEM_BYTES>>>(ffb, wf2w2, ff2_b2, h, h, nullptr, M, D, FF, 0.5f);

    // ---- final LN straight into d_out (fp32) ----
    ln_kernel<false><<<M,128>>>(h, fin_ln_g, fin_ln_b, out);
}

// round 7
// speedup vs baseline: 1.8677x; 1.2985x over previous
#include <cuda_runtime.h>
#include <cuda_bf16.h>
#include <math.h>
#include <stdint.h>

#define Bx 4
#define T 1024
#define D 512
#define H 8
#define DH 64
#define W1 32
#define WB 65
#define FF 2048
#define CE 1024
#define KS 31
#define NTOK (Bx*T)
#define EPS 1e-5f

typedef __nv_bfloat16 bf16;
typedef __nv_bfloat162 bf162;

// ---------------- scratch (static device globals; no allocation) ----------------
__device__ __align__(16) float g_h  [NTOK*D];
__device__ __align__(16) float g_q  [NTOK*D];
__device__ __align__(16) float g_k  [NTOK*D];
__device__ __align__(16) float g_v  [NTOK*D];
__device__ __align__(16) float g_cf [NTOK*CE];
__device__ __align__(16) float g_u  [NTOK*D];
__device__ __align__(16) bf16 g_xb [NTOK*D];
__device__ __align__(16) bf16 g_ffb[NTOK*FF];
__device__ __align__(16) bf16 g_hb [NTOK*D];
__device__ __align__(16) bf16 g_v2b[NTOK*D];
__device__ __align__(16) bf16 wb_f1w1[D*FF];
__device__ __align__(16) bf16 wb_f1w2[FF*D];
__device__ __align__(16) bf16 wb_f2w1[D*FF];
__device__ __align__(16) bf16 wb_f2w2[FF*D];
__device__ __align__(16) bf16 wb_q  [D*D];
__device__ __align__(16) bf16 wb_k  [D*D];
__device__ __align__(16) bf16 wb_v  [D*D];
__device__ __align__(16) bf16 wb_p1 [D*CE];
__device__ __align__(16) bf16 wb_p2 [D*D];

// ---------------- PTX helpers ----------------
__device__ __forceinline__ void mma_bf16(float* c, const uint32_t* a, const uint32_t* b){
    asm volatile(
        "mma.sync.aligned.m16n8k16.row.col.f32.bf16.bf16.f32 "
        "{%0,%1,%2,%3}, {%4,%5,%6,%7}, {%8,%9}, {%0,%1,%2,%3};"
        : "+f"(c[0]), "+f"(c[1]), "+f"(c[2]), "+f"(c[3])
        : "r"(a[0]), "r"(a[1]), "r"(a[2]), "r"(a[3]), "r"(b[0]), "r"(b[1]));
}
__device__ __forceinline__ void ldsm_x4(uint32_t &a, uint32_t &b, uint32_t &c, uint32_t &d, uint32_t addr){
    asm volatile("ldmatrix.sync.aligned.m8n8.x4.shared.b16 {%0,%1,%2,%3}, [%4];"
        : "=r"(a), "=r"(b), "=r"(c), "=r"(d) : "r"(addr));
}
__device__ __forceinline__ void ldsm_x4_t(uint32_t &a, uint32_t &b, uint32_t &c, uint32_t &d, uint32_t addr){
    asm volatile("ldmatrix.sync.aligned.m8n8.x4.trans.shared.b16 {%0,%1,%2,%3}, [%4];"
        : "=r"(a), "=r"(b), "=r"(c), "=r"(d) : "r"(addr));
}
__device__ __forceinline__ void cpasync16(void* smem, const void* g){
    uint32_t s = (uint32_t)__cvta_generic_to_shared(smem);
    asm volatile("cp.async.cg.shared.global [%0], [%1], 16;" :: "r"(s), "l"(g));
}
__device__ __forceinline__ void cp_commit(){ asm volatile("cp.async.commit_group;"); }
template<int N> __device__ __forceinline__ void cp_wait(){ asm volatile("cp.async.wait_group %0;" :: "n"(N)); }

__device__ __forceinline__ uint32_t pack_bf2(float a, float b){
    bf162 p = __floats2bfloat162_rn(a, b);
    return *(uint32_t*)&p;
}

// ---------------- fused weight fp32 -> bf16 (one launch, 22 units of 256K elems) ----------------
struct WCvt {
    const float4* s[9];
    uint2* d[9];
};
__global__ void wcvt_all_kernel(WCvt wc){
    const unsigned char tmap[22] = {0,0,0,0, 1,1,1,1, 2,2,2,2, 3,3,3,3, 4,5,6, 7,7, 8};
    const unsigned char omap[22] = {0,1,2,3, 0,1,2,3, 0,1,2,3, 0,1,2,3, 0,0,0, 0,1, 0};
    int u = blockIdx.y;
    int t = tmap[u];
    size_t i = (size_t)omap[u]*65536 + blockIdx.x*256 + threadIdx.x;   // float4 units
    float4 v = wc.s[t][i];
    uint2 o;
    o.x = pack_bf2(v.x, v.y);
    o.y = pack_bf2(v.z, v.w);
    wc.d[t][i] = o;
}

// ---------------- LayerNorm (row of 512) ----------------
__device__ __forceinline__ float warpSum(float v){
    #pragma unroll
    for (int o=16;o;o>>=1) v += __shfl_xor_sync(0xffffffffu, v, o);
    return v;
}

template<bool B16OUT>
__global__ void ln_kernel(const float* __restrict__ X, const float* __restrict__ gam,
                          const float* __restrict__ bet, void* __restrict__ Yv){
    int row = blockIdx.x;
    int tid = threadIdx.x;
    const float4* x4 = (const float4*)(X + (size_t)row*D);
    float4 v = x4[tid];
    float s  = v.x+v.y+v.z+v.w;
    float ss = v.x*v.x+v.y*v.y+v.z*v.z+v.w*v.w;
    __shared__ float red[8];
    s = warpSum(s); ss = warpSum(ss);
    int wid = tid>>5, lane = tid&31;
    if (lane==0){ red[wid]=s; red[4+wid]=ss; }
    __syncthreads();
    if (tid==0){
        float ts  = red[0]+red[1]+red[2]+red[3];
        float tss = red[4]+red[5]+red[6]+red[7];
        float mean = ts*(1.0f/D);
        float var  = tss*(1.0f/D) - mean*mean;
        red[0]=mean; red[1]=rsqrtf(var + EPS);
    }
    __syncthreads();
    float mean = red[0], rstd = red[1];
    float4 g = ((const float4*)gam)[tid];
    float4 b = ((const float4*)bet)[tid];
    float4 o;
    o.x=(v.x-mean)*rstd*g.x+b.x; o.y=(v.y-mean)*rstd*g.y+b.y;
    o.z=(v.z-mean)*rstd*g.z+b.z; o.w=(v.w-mean)*rstd*g.w+b.w;
    if (B16OUT){
        uint2 u; u.x = pack_bf2(o.x,o.y); u.y = pack_bf2(o.z,o.w);
        *(uint2*)((bf16*)Yv + (size_t)row*D + tid*4) = u;
    } else {
        ((float4*)((float*)Yv + (size_t)row*D))[tid]=o;
    }
}

// ---------------- bf16 tensor-core GEMM 128x128, BK=32, 3-stage cp.async ----------------
#define ASTR 40
#define BSTR 136
#define A_H (128*ASTR)
#define B_H (32*BSTR)
#define STAGE_H (A_H + B_H)
#define STAGES 3
#define GSMEM_BYTES (STAGES*STAGE_H*2)

__device__ __forceinline__ void gemm_core(
    const bf16* __restrict__ Ag, const bf16* __restrict__ Bg,
    int K, int N, float acc[4][4][4], bf16* sm,
    int wm, int wn)
{
    const int tid  = threadIdx.x;
    const int lane = tid & 31;
    const int nk = K >> 5;

    const int ac0 = tid, ac1 = tid + 256;
    const int bc0 = tid, bc1 = tid + 256;

    auto issue = [&](int tile, int stage){
        bf16* as = sm + stage*STAGE_H;
        bf16* bs = as + A_H;
        {
            int r = ac0>>2, kc = ac0&3;
            cpasync16(as + r*ASTR + kc*8, Ag + (size_t)r*K + tile*32 + kc*8);
            r = ac1>>2; kc = ac1&3;
            cpasync16(as + r*ASTR + kc*8, Ag + (size_t)r*K + tile*32 + kc*8);
        }
        {
            int r = bc0>>4, nc = bc0&15;
            cpasync16(bs + r*BSTR + nc*8, Bg + (size_t)(tile*32 + r)*N + nc*8);
            r = bc1>>4; nc = bc1&15;
            cpasync16(bs + r*BSTR + nc*8, Bg + (size_t)(tile*32 + r)*N + nc*8);
        }
    };

    issue(0, 0); cp_commit();
    issue(1, 1); cp_commit();

    const int aoff = (wm*64 + (lane & 15))*ASTR + (lane >> 4)*8;
    const int boff = (((lane >> 4) << 3) + (lane & 7))*BSTR + wn*32 + ((lane >> 3) & 1)*8;

    for (int it=0; it<nk; it++){
        int cur = it % STAGES;
        cp_wait<1>();
        __syncthreads();
        if (it+2 < nk) issue(it+2, (it+2)%STAGES);
        cp_commit();

        bf16* as = sm + cur*STAGE_H;
        bf16* bs = as + A_H;
        uint32_t asb = (uint32_t)__cvta_generic_to_shared(as);
        uint32_t bsb = (uint32_t)__cvta_generic_to_shared(bs);

        #pragma unroll
        for (int ks=0; ks<2; ks++){
            uint32_t af[4][4];
            #pragma unroll
            for (int mi=0; mi<4; mi++){
                uint32_t addr = asb + (uint32_t)(aoff + mi*16*ASTR + ks*16)*2u;
                ldsm_x4(af[mi][0], af[mi][1], af[mi][2], af[mi][3], addr);
            }
            uint32_t bf[4][2];
            #pragma unroll
            for (int p=0; p<2; p++){
                uint32_t addr = bsb + (uint32_t)(boff + ks*16*BSTR + p*16)*2u;
                ldsm_x4_t(bf[p*2][0], bf[p*2+1][0], bf[p*2][1], bf[p*2+1][1], addr);
            }
            #pragma unroll
            for (int mi=0; mi<4; mi++)
                #pragma unroll
                for (int ni=0; ni<4; ni++)
                    mma_bf16(acc[mi][ni], af[mi], bf[ni]);
        }
    }
}

// MODE: 0 = C_f32=AW+bias ; 1 = Cb_bf16=swish(AW+bias) ; 2 = C_f32=R+alpha*(AW+bias) (+bf16 if WB16)
template<int MODE, bool WB16>
__global__ __launch_bounds__(256, 2) void tgemm_kernel(
    const bf16* __restrict__ A, const bf16* __restrict__ W,
    const float* __restrict__ bias, const float* __restrict__ R,
    float* __restrict__ C, bf16* __restrict__ Cb,
    int M, int N, int K, float alpha)
{
    extern __shared__ bf16 smem[];

    const int tid  = threadIdx.x;
    const int lane = tid & 31;
    const int wid  = tid >> 5;
    const int wm   = wid >> 2;
    const int wn   = wid & 3;
    const int bx = blockIdx.x, by = blockIdx.y;
    const int r  = lane >> 2;
    const int cc = lane & 3;

    const bf16* Ag = A + (size_t)(by*128)*K;
    const bf16* Bg = W + bx*128;

    float acc[4][4][4];
    #pragma unroll
    for (int i=0;i<4;i++)
        #pragma unroll
        for (int j=0;j<4;j++)
            #pragma unroll
            for (int q=0;q<4;q++) acc[i][j][q]=0.0f;

    gemm_core(Ag, Bg, K, N, acc, smem, wm, wn);

    #pragma unroll
    for (int mi=0; mi<4; mi++){
        int gr0 = by*128 + wm*64 + mi*16 + r;
        #pragma unroll
        for (int ni=0; ni<4; ni++){
            int col = bx*128 + wn*32 + ni*8 + cc*2;
            float b0 = bias[col], b1 = bias[col+1];
            #pragma unroll
            for (int half=0; half<2; half++){
                int row = gr0 + half*8;
                float v0 = acc[mi][ni][half*2+0] + b0;
                float v1 = acc[mi][ni][half*2+1] + b1;
                if (MODE==1){
                    v0 = v0/(1.0f+expf(-v0)); v1 = v1/(1.0f+expf(-v1));
                    *(uint32_t*)(Cb + (size_t)row*N + col) = pack_bf2(v0, v1);
                }
                if (MODE==0){
                    *(float2*)(C + (size_t)row*N + col) = make_float2(v0, v1);
                }
                if (MODE==2){
                    const float2 rr = *(const float2*)(R + (size_t)row*N + col);
                    v0 = rr.x + alpha*v0; v1 = rr.y + alpha*v1;
                    *(float2*)(C + (size_t)row*N + col) = make_float2(v0, v1);
                    if (WB16)
                        *(uint32_t*)(Cb + (size_t)row*N + col) = pack_bf2(v0, v1);
                }
            }
        }
    }
}

// Fused QKV (bf16 A/W, fp32 out)
__global__ __launch_bounds__(256, 2) void qkv_kernel(
    const bf16* __restrict__ A,
    const bf16* __restrict__ Wq, const bf16* __restrict__ Wk, const bf16* __restrict__ Wv,
    const float* __restrict__ bq, const float* __restrict__ bk, const float* __restrict__ bv,
    float* __restrict__ Q, float* __restrict__ Ko, float* __restrict__ V)
{
    extern __shared__ bf16 smem[];

    const int tid  = threadIdx.x;
    const int lane = tid & 31;
    const int wid  = tid >> 5;
    const int wm   = wid >> 2;
    const int wn   = wid & 3;
    const int by = blockIdx.y;
    const int sel = blockIdx.x >> 2;
    const int bx  = blockIdx.x & 3;
    const int r  = lane >> 2;
    const int cc = lane & 3;

    const bf16* W  = sel==0 ? Wq : (sel==1 ? Wk : Wv);
    const float* bb = sel==0 ? bq : (sel==1 ? bk : bv);
    float* C        = sel==0 ? Q  : (sel==1 ? Ko : V);
    const float alpha = sel==0 ? 0.125f : 1.0f;

    const bf16* Ag = A + (size_t)(by*128)*D;
    const bf16* Bg = W + bx*128;

    float acc[4][4][4];
    #pragma unroll
    for (int i=0;i<4;i++)
        #pragma unroll
        for (int j=0;j<4;j++)
            #pragma unroll
            for (int q=0;q<4;q++) acc[i][j][q]=0.0f;

    gemm_core(Ag, Bg, D, D, acc, smem, wm, wn);

    #pragma unroll
    for (int mi=0; mi<4; mi++){
        int gr0 = by*128 + wm*64 + mi*16 + r;
        #pragma unroll
        for (int ni=0; ni<4; ni++){
            int col = bx*128 + wn*32 + ni*8 + cc*2;
            float b0 = bb[col], b1 = bb[col+1];
            #pragma unroll
            for (int half=0; half<2; half++){
                int row = gr0 + half*8;
                float v0 = (acc[mi][ni][half*2+0] + b0) * alpha;
                float v1 = (acc[mi][ni][half*2+1] + b1) * alpha;
                *(float2*)(C + (size_t)row*D + col) = make_float2(v0, v1);
            }
        }
    }
}

// ---------------- banded attention v2: smem-tiled, CTA per (b,h,64-query block) ----------------
#define TBLK 64
#define KR 128                 // rows in K/V tile: [t0-32, t0+95]
#define RSTR 68                // row stride (floats): float4-aligned, conflict-free
#define QS_F (TBLK*RSTR)       // 4352
#define KS_F (KR*RSTR)         // 8704
#define PS_F (8*RSTR)
#define ATTN_SMEM ((QS_F + 2*KS_F + PS_F)*4)   // 89,216 B

__global__ __launch_bounds__(256, 2) void attn2_kernel(
    const float* __restrict__ Q, const float* __restrict__ Kt,
    const float* __restrict__ V, float* __restrict__ Hh,
    float* __restrict__ P)
{
    extern __shared__ float sm[];
    float* Qs = sm;
    float* Ks = Qs + QS_F;
    float* Vs = Ks + KS_F;
    float* Ps = Vs + KS_F;

    const int tid  = threadIdx.x;
    const int lane = tid & 31;
    const int wq   = tid >> 5;
    const int t0 = blockIdx.x * TBLK;
    const int h  = blockIdx.y;
    const int b  = blockIdx.z;

    const float* Qb = Q + ((size_t)(b*T))*D + h*DH;
    const float* Kb = Kt + ((size_t)(b*T))*D + h*DH;
    const float* Vb = V + ((size_t)(b*T))*D + h*DH;

    // load Q tile (64 rows x 16 float4)
    for (int e = tid; e < TBLK*16; e += 256){
        int i = e >> 4, d4 = e & 15;
        float4 v = *(const float4*)(Qb + (size_t)(t0 + i)*D + d4*4);
        *(float4*)(Qs + i*RSTR + d4*4) = v;
    }
    // load K/V tiles (128 rows x 16 float4), zero-fill out of range
    for (int e = tid; e < KR*16; e += 256){
        int i = e >> 4, d4 = e & 15;
        int src = t0 - W1 + i;
        float4 kv = make_float4(0.f,0.f,0.f,0.f), vv = kv;
        if ((unsigned)src < (unsigned)T){
            kv = *(const float4*)(Kb + (size_t)src*D + d4*4);
            vv = *(const float4*)(Vb + (size_t)src*D + d4*4);
        }
        *(float4*)(Ks + i*RSTR + d4*4) = kv;
        *(float4*)(Vs + i*RSTR + d4*4) = vv;
    }
    __syncthreads();

    for (int qi=0; qi<8; qi++){
        int tq = wq*8 + qi;                // 0..63
        int t  = t0 + tq;

        // scores: lane handles w = lane, lane+32; lane0 also w=64
        float s0 = 0.f, s1 = 0.f, s2 = 0.f;
        {
            const float4* qrow = (const float4*)(Qs + tq*RSTR);
            const float4* k0 = (const float4*)(Ks + (tq + lane)*RSTR);
            const float4* k1 = (const float4*)(Ks + (tq + lane + 32)*RSTR);
            const float4* k2 = (const float4*)(Ks + (tq + 64)*RSTR);
            #pragma unroll
            for (int d4=0; d4<16; d4++){
                float4 qv = qrow[d4];
                float4 a = k0[d4];
                s0 += qv.x*a.x + qv.y*a.y + qv.z*a.z + qv.w*a.w;
                float4 c = k1[d4];
                s1 += qv.x*c.x + qv.y*c.y + qv.z*c.z + qv.w*c.w;
                if (lane==0){
                    float4 e2 = k2[d4];
                    s2 += qv.x*e2.x + qv.y*e2.y + qv.z*e2.z + qv.w*e2.w;
                }
            }
        }
        // mask
        {
            int src0 = t - W1 + lane;
            int src1 = src0 + 32;
            if ((unsigned)src0 >= (unsigned)T) s0 = -1e9f;
            if ((unsigned)src1 >= (unsigned)T) s1 = -1e9f;
            // w=64: src = t+32
            if (lane!=0 || (unsigned)(t + W1) >= (unsigned)T) s2 = -1e30f;
        }
        // softmax over 65 scores
        float m = fmaxf(fmaxf(s0, s1), s2);
        #pragma unroll
        for (int o=16;o;o>>=1) m = fmaxf(m, __shfl_xor_sync(0xffffffffu, m, o));
        float e0 = expf(s0 - m);
        float e1 = expf(s1 - m);
        float e2 = (lane==0) ? expf(s2 - m) : 0.f;
        float sum = e0 + e1 + e2;
        #pragma unroll
        for (int o=16;o;o>>=1) sum += __shfl_xor_sync(0xffffffffu, sum, o);
        float inv = 1.0f / sum;

        // write probs + stash in smem for ctx phase
        float* pp = P + ((size_t)((b*T + t)*H + h))*WB;
        float p0 = e0*inv, p1 = e1*inv;
        pp[lane]      = p0;
        pp[lane + 32] = p1;
        Ps[wq*RSTR + lane]      = p0;
        Ps[wq*RSTR + lane + 32] = p1;
        if (lane==0){
            float p2 = e2*inv;
            pp[64] = p2;
            Ps[wq*RSTR + 64] = p2;
        }
        __syncwarp();

        // ctx: lane handles dims (2*lane, 2*lane+1)
        float a0 = 0.f, a1 = 0.f;
        const float* ps = Ps + wq*RSTR;
        #pragma unroll 5
        for (int w=0; w<WB; w++){
            float p = ps[w];
            float2 vv = *(const float2*)(Vs + (tq + w)*RSTR + 2*lane);
            a0 += p*vv.x;
            a1 += p*vv.y;
        }
        size_t ob = ((size_t)(b*T + t))*D + h*DH + 2*lane;
        float2 hv = *(float2*)(Hh + ob);
        hv.x += a0; hv.y += a1;
        *(float2*)(Hh + ob) = hv;
        __syncwarp();
    }
}

// ---------------- GLU ----------------
__global__ void glu_kernel(const float* __restrict__ CF, float* __restrict__ U){
    int idx = blockIdx.x*blockDim.x + threadIdx.x;
    int r = idx >> 9;
    int c = idx & (D-1);
    float a = CF[(size_t)r*CE + c];
    float g = CF[(size_t)r*CE + D + c];
    U[idx] = a / (1.0f + expf(-g));
}

// ---------------- depthwise conv v2: 4 outputs/thread, register sliding window ----------------
__global__ void dwconv_kernel(const float* __restrict__ U, const float* __restrict__ Wd,
                              const float* __restrict__ bd, const float* __restrict__ bg,
                              const float* __restrict__ bb, bf16* __restrict__ O){
    int idx = blockIdx.x*blockDim.x + threadIdx.x;   // NTOK/4 * D threads
    int c  = idx & (D-1);
    int tt = idx >> 9;                                // token-group index
    int tg = tt & (T/4 - 1);
    int b  = tt >> 8;
    int t4 = tg*4;

    float xv[34];
    #pragma unroll
    for (int i=0;i<34;i++){
        int src = t4 - 15 + i;
        xv[i] = ((unsigned)src < (unsigned)T) ? U[((size_t)(b*T+src))*D + c] : 0.f;
    }
    float base = bd[c];
    float acc0=base, acc1=base, acc2=base, acc3=base;
    #pragma unroll
    for (int k=0;k<KS;k++){
        float w = Wd[k*D + c];
        acc0 = fmaf(xv[k+0], w, acc0);
        acc1 = fmaf(xv[k+1], w, acc1);
        acc2 = fmaf(xv[k+2], w, acc2);
        acc3 = fmaf(xv[k+3], w, acc3);
    }
    const float bns = 0.99999500003749937f;           // rsqrt(1+1e-5)
    float g = bg[c], bb_ = bb[c];
    float r0 = acc0*bns*g + bb_;
    float r1 = acc1*bns*g + bb_;
    float r2 = acc2*bns*g + bb_;
    float r3 = acc3*bns*g + bb_;
    r0 = r0/(1.0f+expf(-r0));
    r1 = r1/(1.0f+expf(-r1));
    r2 = r2/(1.0f+expf(-r2));
    r3 = r3/(1.0f+expf(-r3));
    size_t ob = ((size_t)(b*T + t4))*D + c;
    O[ob        ] = __float2bfloat16_rn(r0);
    O[ob +   D  ] = __float2bfloat16_rn(r1);
    O[ob + 2*D  ] = __float2bfloat16_rn(r2);
    O[ob + 3*D  ] = __float2bfloat16_rn(r3);
}

// ---------------- host ----------------
template<typename Tp>
static Tp* symaddr(const void* s){
    void* p = nullptr;
    cudaGetSymbolAddress(&p, s);
    return (Tp*)p;
}

extern "C" void kernel_launch(void* const* d_in, const int* in_sizes, int n_in,
                              void* d_out, int out_size){
    const float* x         = (const float*)d_in[0];
    const float* ff1_ln_g  = (const float*)d_in[1];
    const float* ff1_ln_b  = (const float*)d_in[2];
    const float* ff1_w1    = (const float*)d_in[3];
    const float* ff1_b1    = (const float*)d_in[4];
    const float* ff1_w2    = (const float*)d_in[5];
    const float* ff1_b2    = (const float*)d_in[6];
    const float* ff2_ln_g  = (const float*)d_in[7];
    const float* ff2_ln_b  = (const float*)d_in[8];
    const float* ff2_w1    = (const float*)d_in[9];
    const float* ff2_b1    = (const float*)d_in[10];
    const float* ff2_w2    = (const float*)d_in[11];
    const float* ff2_b2    = (const float*)d_in[12];
    const float* wq        = (const float*)d_in[13];
    const float* bq        = (const float*)d_in[14];
    const float* wk        = (const float*)d_in[15];
    const float* bk        = (const float*)d_in[16];
    const float* wv        = (const float*)d_in[17];
    const float* bv        = (const float*)d_in[18];
    const float* conv_ln_g = (const float*)d_in[19];
    const float* conv_ln_b = (const float*)d_in[20];
    const float* pw1_w     = (const float*)d_in[21];
    const float* pw1_b     = (const float*)d_in[22];
    const float* dw_w      = (const float*)d_in[23];
    const float* dw_b      = (const float*)d_in[24];
    const float* bn_g      = (const float*)d_in[25];
    const float* bn_b      = (const float*)d_in[26];
    const float* pw2_w     = (const float*)d_in[27];
    const float* pw2_b     = (const float*)d_in[28];
    const float* fin_ln_g  = (const float*)d_in[29];
    const float* fin_ln_b  = (const float*)d_in[30];

    float* out   = (float*)d_out;
    float* probs = out + (size_t)NTOK*D;

    float* h   = symaddr<float>(g_h);
    float* q   = symaddr<float>(g_q);
    float* k   = symaddr<float>(g_k);
    float* v   = symaddr<float>(g_v);
    float* cf  = symaddr<float>(g_cf);
    float* u   = symaddr<float>(g_u);
    bf16* xb   = symaddr<bf16>(g_xb);
    bf16* ffb  = symaddr<bf16>(g_ffb);
    bf16* hb   = symaddr<bf16>(g_hb);
    bf16* v2b  = symaddr<bf16>(g_v2b);
    bf16* wf1w1 = symaddr<bf16>(wb_f1w1);
    bf16* wf1w2 = symaddr<bf16>(wb_f1w2);
    bf16* wf2w1 = symaddr<bf16>(wb_f2w1);
    bf16* wf2w2 = symaddr<bf16>(wb_f2w2);
    bf16* wbq   = symaddr<bf16>(wb_q);
    bf16* wbk   = symaddr<bf16>(wb_k);
    bf16* wbv   = symaddr<bf16>(wb_v);
    bf16* wbp1  = symaddr<bf16>(wb_p1);
    bf16* wbp2  = symaddr<bf16>(wb_p2);

    cudaFuncSetAttribute(tgemm_kernel<0,false>, cudaFuncAttributeMaxDynamicSharedMemorySize, GSMEM_BYTES);
    cudaFuncSetAttribute(tgemm_kernel<1,false>, cudaFuncAttributeMaxDynamicSharedMemorySize, GSMEM_BYTES);
    cudaFuncSetAttribute(tgemm_kernel<2,true>,  cudaFuncAttributeMaxDynamicSharedMemorySize, GSMEM_BYTES);
    cudaFuncSetAttribute(tgemm_kernel<2,false>, cudaFuncAttributeMaxDynamicSharedMemorySize, GSMEM_BYTES);
    cudaFuncSetAttribute(qkv_kernel,            cudaFuncAttributeMaxDynamicSharedMemorySize, GSMEM_BYTES);
    cudaFuncSetAttribute(attn2_kernel,          cudaFuncAttributeMaxDynamicSharedMemorySize, ATTN_SMEM);

    const int M = NTOK;
    dim3 blk(256);

    // ---- (1) fused weight conversion ----
    {
        WCvt wc;
        wc.s[0]=(const float4*)ff1_w1; wc.d[0]=(uint2*)wf1w1;
        wc.s[1]=(const float4*)ff1_w2; wc.d[1]=(uint2*)wf1w2;
        wc.s[2]=(const float4*)ff2_w1; wc.d[2]=(uint2*)wf2w1;
        wc.s[3]=(const float4*)ff2_w2; wc.d[3]=(uint2*)wf2w2;
        wc.s[4]=(const float4*)wq;     wc.d[4]=(uint2*)wbq;
        wc.s[5]=(const float4*)wk;     wc.d[5]=(uint2*)wbk;
        wc.s[6]=(const float4*)wv;     wc.d[6]=(uint2*)wbv;
        wc.s[7]=(const float4*)pw1_w;  wc.d[7]=(uint2*)wbp1;
        wc.s[8]=(const float4*)pw2_w;  wc.d[8]=(uint2*)wbp2;
        wcvt_all_kernel<<<dim3(256,22), 256>>>(wc);
    }

    // ---- ff1 (half-scale residual) ----
    ln_kernel<true><<<M,128>>>(x, ff1_ln_g, ff1_ln_b, xb);                                   // (2)
    tgemm_kernel<1,false><<<dim3(FF/128, M/128), blk, GSMEM_BYTES>>>(xb, wf1w1, ff1_b1, nullptr, nullptr, ffb, M, FF, D, 1.0f);  // (3)
    tgemm_kernel<2,true ><<<dim3(D/128,  M/128), blk, GSMEM_BYTES>>>(ffb, wf1w2, ff1_b2, x, h, hb, M, D, FF, 0.5f);              // (4)

    // ---- QKV ----
    qkv_kernel<<<dim3(12, M/128), blk, GSMEM_BYTES>>>(hb, wbq, wbk, wbv, bq, bk, bv, q, k, v);  // (5)

    // ---- banded attention v2 (launch #6 -> profiled) ----
    attn2_kernel<<<dim3(T/TBLK, H, Bx), blk, ATTN_SMEM>>>(q, k, v, h, probs);                   // (6)

    // ---- conv module (residual in place) ----
    ln_kernel<true><<<M,128>>>(h, conv_ln_g, conv_ln_b, xb);
    tgemm_kernel<0,false><<<dim3(CE/128, M/128), blk, GSMEM_BYTES>>>(xb, wbp1, pw1_b, nullptr, cf, nullptr, M, CE, D, 1.0f);
    glu_kernel<<<(NTOK*D)/256, 256>>>(cf, u);
    dwconv_kernel<<<(NTOK*D/4)/256, 256>>>(u, dw_w, dw_b, bn_g, bn_b, v2b);
    tgemm_kernel<2,false><<<dim3(D/128, M/128), blk, GSMEM_BYTES>>>(v2b, wbp2, pw2_b, h, h, nullptr, M, D, D, 1.0f);

    // ---- ff2 (half-scale residual, in place) ----
    ln_kernel<true><<<M,128>>>(h, ff2_ln_g, ff2_ln_b, xb);
    tgemm_kernel<1,false><<<dim3(FF/128, M/128), blk, GSMEM_BYTES>>>(xb, wf2w1, ff2_b1, nullptr, nullptr, ffb, M, FF, D, 1.0f);
    tgemm_kernel<2,false><<<dim3(D/128,  M/128), blk, GSMEM_BYTES>>>(ffb, wf2w2, ff2_b2, h, h, nullptr, M, D, FF, 0.5f);

    // ---- final LN straight into d_out (fp32) ----
    ln_kernel<false><<<M,128>>>(h, fin_ln_g, fin_ln_b, out);
}

// round 9
// speedup vs baseline: 1.8884x; 1.0111x over previous
#include <cuda_runtime.h>
#include <cuda_bf16.h>
#include <math.h>
#include <stdint.h>

#define Bx 4
#define T 1024
#define D 512
#define H 8
#define DH 64
#define W1 32
#define WB 65
#define FF 2048
#define CE 1024
#define KS 31
#define NTOK (Bx*T)
#define EPS 1e-5f

typedef __nv_bfloat16 bf16;
typedef __nv_bfloat162 bf162;

// ---------------- scratch (static device globals; no allocation) ----------------
__device__ __align__(16) float g_h  [NTOK*D];
__device__ __align__(16) float g_q  [NTOK*D];
__device__ __align__(16) float g_k  [NTOK*D];
__device__ __align__(16) float g_v  [NTOK*D];
__device__ __align__(16) float g_cf [NTOK*CE];
__device__ __align__(16) float g_u  [NTOK*D];
__device__ __align__(16) bf16 g_xb [NTOK*D];
__device__ __align__(16) bf16 g_ffb[NTOK*FF];
__device__ __align__(16) bf16 g_hb [NTOK*D];
__device__ __align__(16) bf16 g_v2b[NTOK*D];
__device__ __align__(16) bf16 wb_f1w1[D*FF];
__device__ __align__(16) bf16 wb_f1w2[FF*D];
__device__ __align__(16) bf16 wb_f2w1[D*FF];
__device__ __align__(16) bf16 wb_f2w2[FF*D];
__device__ __align__(16) bf16 wb_q  [D*D];
__device__ __align__(16) bf16 wb_k  [D*D];
__device__ __align__(16) bf16 wb_v  [D*D];
__device__ __align__(16) bf16 wb_p1 [D*CE];
__device__ __align__(16) bf16 wb_p2 [D*D];

// ---------------- PTX helpers ----------------
__device__ __forceinline__ void mma_bf16(float* c, const uint32_t* a, const uint32_t* b){
    asm volatile(
        "mma.sync.aligned.m16n8k16.row.col.f32.bf16.bf16.f32 "
        "{%0,%1,%2,%3}, {%4,%5,%6,%7}, {%8,%9}, {%0,%1,%2,%3};"
        : "+f"(c[0]), "+f"(c[1]), "+f"(c[2]), "+f"(c[3])
        : "r"(a[0]), "r"(a[1]), "r"(a[2]), "r"(a[3]), "r"(b[0]), "r"(b[1]));
}
__device__ __forceinline__ void ldsm_x4(uint32_t &a, uint32_t &b, uint32_t &c, uint32_t &d, uint32_t addr){
    asm volatile("ldmatrix.sync.aligned.m8n8.x4.shared.b16 {%0,%1,%2,%3}, [%4];"
        : "=r"(a), "=r"(b), "=r"(c), "=r"(d) : "r"(addr));
}
__device__ __forceinline__ void ldsm_x4_t(uint32_t &a, uint32_t &b, uint32_t &c, uint32_t &d, uint32_t addr){
    asm volatile("ldmatrix.sync.aligned.m8n8.x4.trans.shared.b16 {%0,%1,%2,%3}, [%4];"
        : "=r"(a), "=r"(b), "=r"(c), "=r"(d) : "r"(addr));
}
__device__ __forceinline__ void cpasync16(void* smem, const void* g){
    uint32_t s = (uint32_t)__cvta_generic_to_shared(smem);
    asm volatile("cp.async.cg.shared.global [%0], [%1], 16;" :: "r"(s), "l"(g));
}
__device__ __forceinline__ void cp_commit(){ asm volatile("cp.async.commit_group;"); }
template<int N> __device__ __forceinline__ void cp_wait(){ asm volatile("cp.async.wait_group %0;" :: "n"(N)); }

__device__ __forceinline__ uint32_t pack_bf2(float a, float b){
    bf162 p = __floats2bfloat162_rn(a, b);
    return *(uint32_t*)&p;
}

// ---------------- fused weight fp32 -> bf16 (one launch) ----------------
struct WCvt {
    const float4* s[9];
    uint2* d[9];
};
__global__ void wcvt_all_kernel(WCvt wc){
    const unsigned char tmap[22] = {0,0,0,0, 1,1,1,1, 2,2,2,2, 3,3,3,3, 4,5,6, 7,7, 8};
    const unsigned char omap[22] = {0,1,2,3, 0,1,2,3, 0,1,2,3, 0,1,2,3, 0,0,0, 0,1, 0};
    int u = blockIdx.y;
    int t = tmap[u];
    size_t i = (size_t)omap[u]*65536 + blockIdx.x*256 + threadIdx.x;
    float4 v = wc.s[t][i];
    uint2 o;
    o.x = pack_bf2(v.x, v.y);
    o.y = pack_bf2(v.z, v.w);
    wc.d[t][i] = o;
}

// ---------------- LayerNorm (row of 512) ----------------
__device__ __forceinline__ float warpSum(float v){
    #pragma unroll
    for (int o=16;o;o>>=1) v += __shfl_xor_sync(0xffffffffu, v, o);
    return v;
}

template<bool B16OUT>
__global__ void ln_kernel(const float* __restrict__ X, const float* __restrict__ gam,
                          const float* __restrict__ bet, void* __restrict__ Yv){
    int row = blockIdx.x;
    int tid = threadIdx.x;
    const float4* x4 = (const float4*)(X + (size_t)row*D);
    float4 v = x4[tid];
    float s  = v.x+v.y+v.z+v.w;
    float ss = v.x*v.x+v.y*v.y+v.z*v.z+v.w*v.w;
    __shared__ float red[8];
    s = warpSum(s); ss = warpSum(ss);
    int wid = tid>>5, lane = tid&31;
    if (lane==0){ red[wid]=s; red[4+wid]=ss; }
    __syncthreads();
    if (tid==0){
        float ts  = red[0]+red[1]+red[2]+red[3];
        float tss = red[4]+red[5]+red[6]+red[7];
        float mean = ts*(1.0f/D);
        float var  = tss*(1.0f/D) - mean*mean;
        red[0]=mean; red[1]=rsqrtf(var + EPS);
    }
    __syncthreads();
    float mean = red[0], rstd = red[1];
    float4 g = ((const float4*)gam)[tid];
    float4 b = ((const float4*)bet)[tid];
    float4 o;
    o.x=(v.x-mean)*rstd*g.x+b.x; o.y=(v.y-mean)*rstd*g.y+b.y;
    o.z=(v.z-mean)*rstd*g.z+b.z; o.w=(v.w-mean)*rstd*g.w+b.w;
    if (B16OUT){
        uint2 u; u.x = pack_bf2(o.x,o.y); u.y = pack_bf2(o.z,o.w);
        *(uint2*)((bf16*)Yv + (size_t)row*D + tid*4) = u;
    } else {
        ((float4*)((float*)Yv + (size_t)row*D))[tid]=o;
    }
}

// ---------------- bf16 tensor-core GEMM, BM = NMI*32 x 128, BK=32, 3-stage ----------------
#define ASTR 40
#define BSTR 136
#define B_H (32*BSTR)
#define STAGES 3
// stage sizes per BM
#define A_H_128 (128*ASTR)
#define A_H_64  (64*ASTR)
#define GSMEM_128 (STAGES*(A_H_128 + B_H)*2)
#define GSMEM_64  (STAGES*(A_H_64  + B_H)*2)

// NMI = number of 16-row M fragments per warp (4 -> BM=128, 2 -> BM=64)
template<int NMI>
__device__ __forceinline__ void gemm_core(
    const bf16* __restrict__ Ag, const bf16* __restrict__ Bg,
    int K, int N, float acc[NMI][4][4], bf16* sm,
    int wm, int wn)
{
    constexpr int BM  = NMI*32;
    constexpr int A_H = BM*ASTR;
    constexpr int STG = A_H + B_H;

    const int tid  = threadIdx.x;
    const int lane = tid & 31;
    const int nk = K >> 5;

    auto issue = [&](int tile, int stage){
        bf16* as = sm + stage*STG;
        bf16* bs = as + A_H;
        #pragma unroll
        for (int c = tid; c < BM*4; c += 256){
            int r = c>>2, kc = c&3;
            cpasync16(as + r*ASTR + kc*8, Ag + (size_t)r*K + tile*32 + kc*8);
        }
        #pragma unroll
        for (int c = tid; c < 512; c += 256){
            int r = c>>4, nc = c&15;
            cpasync16(bs + r*BSTR + nc*8, Bg + (size_t)(tile*32 + r)*N + nc*8);
        }
    };

    issue(0, 0); cp_commit();
    issue(1, 1); cp_commit();

    const int aoff = (wm*(BM/2) + (lane & 15))*ASTR + (lane >> 4)*8;
    const int boff = (((lane >> 4) << 3) + (lane & 7))*BSTR + wn*32 + ((lane >> 3) & 1)*8;

    for (int it=0; it<nk; it++){
        int cur = it % STAGES;
        cp_wait<1>();
        __syncthreads();
        if (it+2 < nk) issue(it+2, (it+2)%STAGES);
        cp_commit();

        bf16* as = sm + cur*STG;
        bf16* bs = as + A_H;
        uint32_t asb = (uint32_t)__cvta_generic_to_shared(as);
        uint32_t bsb = (uint32_t)__cvta_generic_to_shared(bs);

        #pragma unroll
        for (int ks=0; ks<2; ks++){
            uint32_t af[NMI][4];
            #pragma unroll
            for (int mi=0; mi<NMI; mi++){
                uint32_t addr = asb + (uint32_t)(aoff + mi*16*ASTR + ks*16)*2u;
                ldsm_x4(af[mi][0], af[mi][1], af[mi][2], af[mi][3], addr);
            }
            uint32_t bf[4][2];
            #pragma unroll
            for (int p=0; p<2; p++){
                uint32_t addr = bsb + (uint32_t)(boff + ks*16*BSTR + p*16)*2u;
                ldsm_x4_t(bf[p*2][0], bf[p*2+1][0], bf[p*2][1], bf[p*2+1][1], addr);
            }
            #pragma unroll
            for (int mi=0; mi<NMI; mi++)
                #pragma unroll
                for (int ni=0; ni<4; ni++)
                    mma_bf16(acc[mi][ni], af[mi], bf[ni]);
        }
    }
}

// MODE: 0 = C_f32=AW+bias ; 1 = Cb_bf16=swish(AW+bias) ; 2 = C_f32=R+alpha*(AW+bias) (+bf16 if WB16)
template<int MODE, bool WB16, int NMI>
__global__ __launch_bounds__(256, 2) void tgemm_kernel(
    const bf16* __restrict__ A, const bf16* __restrict__ W,
    const float* __restrict__ bias, const float* __restrict__ R,
    float* __restrict__ C, bf16* __restrict__ Cb,
    int M, int N, int K, float alpha)
{
    extern __shared__ bf16 smem[];
    constexpr int BM = NMI*32;

    const int tid  = threadIdx.x;
    const int lane = tid & 31;
    const int wid  = tid >> 5;
    const int wm   = wid >> 2;
    const int wn   = wid & 3;
    const int bx = blockIdx.x, by = blockIdx.y;
    const int r  = lane >> 2;
    const int cc = lane & 3;

    const bf16* Ag = A + (size_t)(by*BM)*K;
    const bf16* Bg = W + bx*128;

    float acc[NMI][4][4];
    #pragma unroll
    for (int i=0;i<NMI;i++)
        #pragma unroll
        for (int j=0;j<4;j++)
            #pragma unroll
            for (int q=0;q<4;q++) acc[i][j][q]=0.0f;

    gemm_core<NMI>(Ag, Bg, K, N, acc, smem, wm, wn);

    #pragma unroll
    for (int mi=0; mi<NMI; mi++){
        int gr0 = by*BM + wm*(BM/2) + mi*16 + r;
        #pragma unroll
        for (int ni=0; ni<4; ni++){
            int col = bx*128 + wn*32 + ni*8 + cc*2;
            float b0 = bias[col], b1 = bias[col+1];
            #pragma unroll
            for (int half=0; half<2; half++){
                int row = gr0 + half*8;
                float v0 = acc[mi][ni][half*2+0] + b0;
                float v1 = acc[mi][ni][half*2+1] + b1;
                if (MODE==1){
                    v0 = v0/(1.0f+expf(-v0)); v1 = v1/(1.0f+expf(-v1));
                    *(uint32_t*)(Cb + (size_t)row*N + col) = pack_bf2(v0, v1);
                }
                if (MODE==0){
                    *(float2*)(C + (size_t)row*N + col) = make_float2(v0, v1);
                }
                if (MODE==2){
                    const float2 rr = *(const float2*)(R + (size_t)row*N + col);
                    v0 = rr.x + alpha*v0; v1 = rr.y + alpha*v1;
                    *(float2*)(C + (size_t)row*N + col) = make_float2(v0, v1);
                    if (WB16)
                        *(uint32_t*)(Cb + (size_t)row*N + col) = pack_bf2(v0, v1);
                }
            }
        }
    }
}

// Fused QKV (bf16 A/W, fp32 out), BM=128
__global__ __launch_bounds__(256, 2) void qkv_kernel(
    const bf16* __restrict__ A,
    const bf16* __restrict__ Wq, const bf16* __restrict__ Wk, const bf16* __restrict__ Wv,
    const float* __restrict__ bq, const float* __restrict__ bk, const float* __restrict__ bv,
    float* __restrict__ Q, float* __restrict__ Ko, float* __restrict__ V)
{
    extern __shared__ bf16 smem[];

    const int tid  = threadIdx.x;
    const int lane = tid & 31;
    const int wid  = tid >> 5;
    const int wm   = wid >> 2;
    const int wn   = wid & 3;
    const int by = blockIdx.y;
    const int sel = blockIdx.x >> 2;
    const int bx  = blockIdx.x & 3;
    const int r  = lane >> 2;
    const int cc = lane & 3;

    const bf16* W  = sel==0 ? Wq : (sel==1 ? Wk : Wv);
    const float* bb = sel==0 ? bq : (sel==1 ? bk : bv);
    float* C        = sel==0 ? Q  : (sel==1 ? Ko : V);
    const float alpha = sel==0 ? 0.125f : 1.0f;

    const bf16* Ag = A + (size_t)(by*128)*D;
    const bf16* Bg = W + bx*128;

    float acc[4][4][4];
    #pragma unroll
    for (int i=0;i<4;i++)
        #pragma unroll
        for (int j=0;j<4;j++)
            #pragma unroll
            for (int q=0;q<4;q++) acc[i][j][q]=0.0f;

    gemm_core<4>(Ag, Bg, D, D, acc, smem, wm, wn);

    #pragma unroll
    for (int mi=0; mi<4; mi++){
        int gr0 = by*128 + wm*64 + mi*16 + r;
        #pragma unroll
        for (int ni=0; ni<4; ni++){
            int col = bx*128 + wn*32 + ni*8 + cc*2;
            float b0 = bb[col], b1 = bb[col+1];
            #pragma unroll
            for (int half=0; half<2; half++){
                int row = gr0 + half*8;
                float v0 = (acc[mi][ni][half*2+0] + b0) * alpha;
                float v1 = (acc[mi][ni][half*2+1] + b1) * alpha;
                *(float2*)(C + (size_t)row*D + col) = make_float2(v0, v1);
            }
        }
    }
}

// ---------------- banded attention v2: smem-tiled, CTA per (b,h,64-query block) ----------------
#define TBLK 64
#define KR 128
#define RSTR 68
#define QS_F (TBLK*RSTR)
#define KS_F (KR*RSTR)
#define PS_F (8*RSTR)
#define ATTN_SMEM ((QS_F + 2*KS_F + PS_F)*4)

__global__ __launch_bounds__(256, 2) void attn2_kernel(
    const float* __restrict__ Q, const float* __restrict__ Kt,
    const float* __restrict__ V, float* __restrict__ Hh,
    float* __restrict__ P)
{
    extern __shared__ float sm[];
    float* Qs = sm;
    float* Ks = Qs + QS_F;
    float* Vs = Ks + KS_F;
    float* Ps = Vs + KS_F;

    const int tid  = threadIdx.x;
    const int lane = tid & 31;
    const int wq   = tid >> 5;
    const int t0 = blockIdx.x * TBLK;
    const int h  = blockIdx.y;
    const int b  = blockIdx.z;

    const float* Qb = Q + ((size_t)(b*T))*D + h*DH;
    const float* Kb = Kt + ((size_t)(b*T))*D + h*DH;
    const float* Vb = V + ((size_t)(b*T))*D + h*DH;

    for (int e = tid; e < TBLK*16; e += 256){
        int i = e >> 4, d4 = e & 15;
        float4 v = *(const float4*)(Qb + (size_t)(t0 + i)*D + d4*4);
        *(float4*)(Qs + i*RSTR + d4*4) = v;
    }
    for (int e = tid; e < KR*16; e += 256){
        int i = e >> 4, d4 = e & 15;
        int src = t0 - W1 + i;
        float4 kv = make_float4(0.f,0.f,0.f,0.f), vv = kv;
        if ((unsigned)src < (unsigned)T){
            kv = *(const float4*)(Kb + (size_t)src*D + d4*4);
            vv = *(const float4*)(Vb + (size_t)src*D + d4*4);
        }
        *(float4*)(Ks + i*RSTR + d4*4) = kv;
        *(float4*)(Vs + i*RSTR + d4*4) = vv;
    }
    __syncthreads();

    for (int qi=0; qi<8; qi++){
        int tq = wq*8 + qi;
        int t  = t0 + tq;

        float s0 = 0.f, s1 = 0.f, s2 = 0.f;
        {
            const float4* qrow = (const float4*)(Qs + tq*RSTR);
            const float4* k0 = (const float4*)(Ks + (tq + lane)*RSTR);
            const float4* k1 = (const float4*)(Ks + (tq + lane + 32)*RSTR);
            const float4* k2 = (const float4*)(Ks + (tq + 64)*RSTR);
            #pragma unroll
            for (int d4=0; d4<16; d4++){
                float4 qv = qrow[d4];
                float4 a = k0[d4];
                s0 += qv.x*a.x + qv.y*a.y + qv.z*a.z + qv.w*a.w;
                float4 c = k1[d4];
                s1 += qv.x*c.x + qv.y*c.y + qv.z*c.z + qv.w*c.w;
                if (lane==0){
                    float4 e2 = k2[d4];
                    s2 += qv.x*e2.x + qv.y*e2.y + qv.z*e2.z + qv.w*e2.w;
                }
            }
        }
        {
            int src0 = t - W1 + lane;
            int src1 = src0 + 32;
            if ((unsigned)src0 >= (unsigned)T) s0 = -1e9f;
            if ((unsigned)src1 >= (unsigned)T) s1 = -1e9f;
            if (lane!=0 || (unsigned)(t + W1) >= (unsigned)T) s2 = -1e30f;
        }
        float m = fmaxf(fmaxf(s0, s1), s2);
        #pragma unroll
        for (int o=16;o;o>>=1) m = fmaxf(m, __shfl_xor_sync(0xffffffffu, m, o));
        float e0 = expf(s0 - m);
        float e1 = expf(s1 - m);
        float e2 = (lane==0) ? expf(s2 - m) : 0.f;
        float sum = e0 + e1 + e2;
        #pragma unroll
        for (int o=16;o;o>>=1) sum += __shfl_xor_sync(0xffffffffu, sum, o);
        float inv = 1.0f / sum;

        float* pp = P + ((size_t)((b*T + t)*H + h))*WB;
        float p0 = e0*inv, p1 = e1*inv;
        pp[lane]      = p0;
        pp[lane + 32] = p1;
        Ps[wq*RSTR + lane]      = p0;
        Ps[wq*RSTR + lane + 32] = p1;
        if (lane==0){
            float p2 = e2*inv;
            pp[64] = p2;
            Ps[wq*RSTR + 64] = p2;
        }
        __syncwarp();

        float a0 = 0.f, a1 = 0.f;
        const float* ps = Ps + wq*RSTR;
        #pragma unroll 5
        for (int w=0; w<WB; w++){
            float p = ps[w];
            float2 vv = *(const float2*)(Vs + (tq + w)*RSTR + 2*lane);
            a0 += p*vv.x;
            a1 += p*vv.y;
        }
        size_t ob = ((size_t)(b*T + t))*D + h*DH + 2*lane;
        float2 hv = *(float2*)(Hh + ob);
        hv.x += a0; hv.y += a1;
        *(float2*)(Hh + ob) = hv;
        __syncwarp();
    }
}

// ---------------- GLU ----------------
__global__ void glu_kernel(const float* __restrict__ CF, float* __restrict__ U){
    int idx = blockIdx.x*blockDim.x + threadIdx.x;
    int r = idx >> 9;
    int c = idx & (D-1);
    float a = CF[(size_t)r*CE + c];
    float g = CF[(size_t)r*CE + D + c];
    U[idx] = a / (1.0f + expf(-g));
}

// ---------------- depthwise conv v2 ----------------
__global__ void dwconv_kernel(const float* __restrict__ U, const float* __restrict__ Wd,
                              const float* __restrict__ bd, const float* __restrict__ bg,
                              const float* __restrict__ bb, bf16* __restrict__ O){
    int idx = blockIdx.x*blockDim.x + threadIdx.x;
    int c  = idx & (D-1);
    int tt = idx >> 9;
    int tg = tt & (T/4 - 1);
    int b  = tt >> 8;
    int t4 = tg*4;

    float xv[34];
    #pragma unroll
    for (int i=0;i<34;i++){
        int src = t4 - 15 + i;
        xv[i] = ((unsigned)src < (unsigned)T) ? U[((size_t)(b*T+src))*D + c] : 0.f;
    }
    float base = bd[c];
    float acc0=base, acc1=base, acc2=base, acc3=base;
    #pragma unroll
    for (int k=0;k<KS;k++){
        float w = Wd[k*D + c];
        acc0 = fmaf(xv[k+0], w, acc0);
        acc1 = fmaf(xv[k+1], w, acc1);
        acc2 = fmaf(xv[k+2], w, acc2);
        acc3 = fmaf(xv[k+3], w, acc3);
    }
    const float bns = 0.99999500003749937f;
    float g = bg[c], bb_ = bb[c];
    float r0 = acc0*bns*g + bb_;
    float r1 = acc1*bns*g + bb_;
    float r2 = acc2*bns*g + bb_;
    float r3 = acc3*bns*g + bb_;
    r0 = r0/(1.0f+expf(-r0));
    r1 = r1/(1.0f+expf(-r1));
    r2 = r2/(1.0f+expf(-r2));
    r3 = r3/(1.0f+expf(-r3));
    size_t ob = ((size_t)(b*T + t4))*D + c;
    O[ob        ] = __float2bfloat16_rn(r0);
    O[ob +   D  ] = __float2bfloat16_rn(r1);
    O[ob + 2*D  ] = __float2bfloat16_rn(r2);
    O[ob + 3*D  ] = __float2bfloat16_rn(r3);
}

// ---------------- host ----------------
template<typename Tp>
static Tp* symaddr(const void* s){
    void* p = nullptr;
    cudaGetSymbolAddress(&p, s);
    return (Tp*)p;
}

extern "C" void kernel_launch(void* const* d_in, const int* in_sizes, int n_in,
                              void* d_out, int out_size){
    const float* x         = (const float*)d_in[0];
    const float* ff1_ln_g  = (const float*)d_in[1];
    const float* ff1_ln_b  = (const float*)d_in[2];
    const float* ff1_w1    = (const float*)d_in[3];
    const float* ff1_b1    = (const float*)d_in[4];
    const float* ff1_w2    = (const float*)d_in[5];
    const float* ff1_b2    = (const float*)d_in[6];
    const float* ff2_ln_g  = (const float*)d_in[7];
    const float* ff2_ln_b  = (const float*)d_in[8];
    const float* ff2_w1    = (const float*)d_in[9];
    const float* ff2_b1    = (const float*)d_in[10];
    const float* ff2_w2    = (const float*)d_in[11];
    const float* ff2_b2    = (const float*)d_in[12];
    const float* wq        = (const float*)d_in[13];
    const float* bq        = (const float*)d_in[14];
    const float* wk        = (const float*)d_in[15];
    const float* bk        = (const float*)d_in[16];
    const float* wv        = (const float*)d_in[17];
    const float* bv        = (const float*)d_in[18];
    const float* conv_ln_g = (const float*)d_in[19];
    const float* conv_ln_b = (const float*)d_in[20];
    const float* pw1_w     = (const float*)d_in[21];
    const float* pw1_b     = (const float*)d_in[22];
    const float* dw_w      = (const float*)d_in[23];
    const float* dw_b      = (const float*)d_in[24];
    const float* bn_g      = (const float*)d_in[25];
    const float* bn_b      = (const float*)d_in[26];
    const float* pw2_w     = (const float*)d_in[27];
    const float* pw2_b     = (const float*)d_in[28];
    const float* fin_ln_g  = (const float*)d_in[29];
    const float* fin_ln_b  = (const float*)d_in[30];

    float* out   = (float*)d_out;
    float* probs = out + (size_t)NTOK*D;

    float* h   = symaddr<float>(g_h);
    float* q   = symaddr<float>(g_q);
    float* k   = symaddr<float>(g_k);
    float* v   = symaddr<float>(g_v);
    float* cf  = symaddr<float>(g_cf);
    float* u   = symaddr<float>(g_u);
    bf16* xb   = symaddr<bf16>(g_xb);
    bf16* ffb  = symaddr<bf16>(g_ffb);
    bf16* hb   = symaddr<bf16>(g_hb);
    bf16* v2b  = symaddr<bf16>(g_v2b);
    bf16* wf1w1 = symaddr<bf16>(wb_f1w1);
    bf16* wf1w2 = symaddr<bf16>(wb_f1w2);
    bf16* wf2w1 = symaddr<bf16>(wb_f2w1);
    bf16* wf2w2 = symaddr<bf16>(wb_f2w2);
    bf16* wbq   = symaddr<bf16>(wb_q);
    bf16* wbk   = symaddr<bf16>(wb_k);
    bf16* wbv   = symaddr<bf16>(wb_v);
    bf16* wbp1  = symaddr<bf16>(wb_p1);
    bf16* wbp2  = symaddr<bf16>(wb_p2);

    cudaFuncSetAttribute((const void*)tgemm_kernel<1,false,4>, cudaFuncAttributeMaxDynamicSharedMemorySize, GSMEM_128);
    cudaFuncSetAttribute((const void*)tgemm_kernel<0,false,4>, cudaFuncAttributeMaxDynamicSharedMemorySize, GSMEM_128);
    cudaFuncSetAttribute((const void*)tgemm_kernel<2,true,2>,  cudaFuncAttributeMaxDynamicSharedMemorySize, GSMEM_64);
    cudaFuncSetAttribute((const void*)tgemm_kernel<2,false,2>, cudaFuncAttributeMaxDynamicSharedMemorySize, GSMEM_64);
    cudaFuncSetAttribute((const void*)qkv_kernel,              cudaFuncAttributeMaxDynamicSharedMemorySize, GSMEM_128);
    cudaFuncSetAttribute((const void*)attn2_kernel,            cudaFuncAttributeMaxDynamicSharedMemorySize, ATTN_SMEM);

    const int M = NTOK;
    dim3 blk(256);

    // ---- fused weight conversion ----
    {
        WCvt wc;
        wc.s[0]=(const float4*)ff1_w1; wc.d[0]=(uint2*)wf1w1;
        wc.s[1]=(const float4*)ff1_w2; wc.d[1]=(uint2*)wf1w2;
        wc.s[2]=(const float4*)ff2_w1; wc.d[2]=(uint2*)wf2w1;
        wc.s[3]=(const float4*)ff2_w2; wc.d[3]=(uint2*)wf2w2;
        wc.s[4]=(const float4*)wq;     wc.d[4]=(uint2*)wbq;
        wc.s[5]=(const float4*)wk;     wc.d[5]=(uint2*)wbk;
        wc.s[6]=(const float4*)wv;     wc.d[6]=(uint2*)wbv;
        wc.s[7]=(const float4*)pw1_w;  wc.d[7]=(uint2*)wbp1;
        wc.s[8]=(const float4*)pw2_w;  wc.d[8]=(uint2*)wbp2;
        wcvt_all_kernel<<<dim3(256,22), 256>>>(wc);
    }

    // ---- ff1 (half-scale residual) ----
    ln_kernel<true><<<M,128>>>(x, ff1_ln_g, ff1_ln_b, xb);
    tgemm_kernel<1,false,4><<<dim3(FF/128, M/128), blk, GSMEM_128>>>(xb, wf1w1, ff1_b1, nullptr, nullptr, ffb, M, FF, D, 1.0f);
    tgemm_kernel<2,true,2 ><<<dim3(D/128,  M/64 ), blk, GSMEM_64 >>>(ffb, wf1w2, ff1_b2, x, h, hb, M, D, FF, 0.5f);

    // ---- QKV ----
    qkv_kernel<<<dim3(12, M/128), blk, GSMEM_128>>>(hb, wbq, wbk, wbv, bq, bk, bv, q, k, v);

    // ---- banded attention v2 ----
    attn2_kernel<<<dim3(T/TBLK, H, Bx), blk, ATTN_SMEM>>>(q, k, v, h, probs);

    // ---- conv module (residual in place) ----
    ln_kernel<true><<<M,128>>>(h, conv_ln_g, conv_ln_b, xb);
    tgemm_kernel<0,false,4><<<dim3(CE/128, M/128), blk, GSMEM_128>>>(xb, wbp1, pw1_b, nullptr, cf, nullptr, M, CE, D, 1.0f);
    glu_kernel<<<(NTOK*D)/256, 256>>>(cf, u);
    dwconv_kernel<<<(NTOK*D/4)/256, 256>>>(u, dw_w, dw_b, bn_g, bn_b, v2b);
    tgemm_kernel<2,false,2><<<dim3(D/128, M/64), blk, GSMEM_64>>>(v2b, wbp2, pw2_b, h, h, nullptr, M, D, D, 1.0f);

    // ---- ff2 (half-scale residual, in place) ----
    ln_kernel<true><<<M,128>>>(h, ff2_ln_g, ff2_ln_b, xb);
    tgemm_kernel<1,false,4><<<dim3(FF/128, M/128), blk, GSMEM_128>>>(xb, wf2w1, ff2_b1, nullptr, nullptr, ffb, M, FF, D, 1.0f);
    tgemm_kernel<2,false,2><<<dim3(D/128,  M/64 ), blk, GSMEM_64>>>(ffb, wf2w2, ff2_b2, h, h, nullptr, M, D, FF, 0.5f);

    // ---- final LN straight into d_out (fp32) ----
    ln_kernel<false><<<M,128>>>(h, fin_ln_g, fin_ln_b, out);
}